// round 4
// baseline (speedup 1.0000x reference)
#include <cuda_runtime.h>
#include <math.h>

// Problem dims
#define BB   64
#define CC   3
#define JJ   25
#define TT   256
#define CO   64
#define ROW  (JJ*TT)            /* 6400 */
#define SIGC 84
#define NPIX (BB*JJ*TT)         /* 409600 per channel */
#define EPSV 1e-5

// ---------------- scratch (static device allocations: allowed) ----------------
__device__ float  g_xconv[(size_t)BB*CO*ROW];   // relu(conv), pre-BN
__device__ float  g_sig  [(size_t)BB*CO*ROW];   // relu(folded ps proj), pre-BN
__device__ float  g_y    [(size_t)BB*CO*ROW];   // relu(folded fu proj), pre-BN
__device__ float  g_Asp[SIGC*CO];
__device__ float  g_Atp[SIGC*CO];
__device__ float  g_psb[CO];
__device__ float  g_fuwT[128*CO];               // [c][o], BN folded in
__device__ float  g_fub[CO];
__device__ double g_part[192*16*2];             // per-(channel-slot, block) partial sum/sumsq
__device__ float  g_bny_scale[CO];
__device__ float  g_bny_shift[CO];

// ---------------- fold1: A_sp = sp_W @ ps_w_left^T, A_tp = tp_W @ ps_w_right^T ----------------
__global__ void k_fold1(const float* __restrict__ spW, const float* __restrict__ spb,
                        const float* __restrict__ tpW, const float* __restrict__ tpb,
                        const float* __restrict__ psw, const float* __restrict__ psb)
{
    int tid = threadIdx.x;
    for (int idx = tid; idx < SIGC*CO; idx += blockDim.x) {
        int i = idx / CO, o = idx % CO;
        float s1 = 0.f, s2 = 0.f;
        for (int c = 0; c < CO; c++) {
            s1 = fmaf(spW[i*CO + c], psw[o*128 + c],      s1);
            s2 = fmaf(tpW[i*CO + c], psw[o*128 + 64 + c], s2);
        }
        g_Asp[idx] = s1;
        g_Atp[idx] = s2;
    }
    if (tid < CO) {
        float bsum = psb[tid];
        for (int c = 0; c < CO; c++) {
            bsum = fmaf(spb[c], psw[tid*128 + c],      bsum);
            bsum = fmaf(tpb[c], psw[tid*128 + 64 + c], bsum);
        }
        g_psb[tid] = bsum;
    }
}

// ---------------- conv (1x3 along T, zero pad) + relu ----------------
__global__ __launch_bounds__(256) void k_conv(const float* __restrict__ x,
                                              const float* __restrict__ cw,
                                              const float* __restrict__ cb)
{
    __shared__ float ws[CO*9];
    __shared__ float bs[CO];
    int j = blockIdx.x, b = blockIdx.y;
    int tid = threadIdx.x, t = tid;
    for (int i = tid; i < CO*9; i += 256) ws[i] = cw[i];
    if (tid < CO) bs[tid] = cb[tid];
    __syncthreads();

    float xv[9];
#pragma unroll
    for (int c = 0; c < 3; c++) {
        const float* xr = x + (((size_t)b*3 + c)*JJ + j)*TT;
        xv[c*3+0] = (t > 0)     ? xr[t-1] : 0.f;
        xv[c*3+1] = xr[t];
        xv[c*3+2] = (t < TT-1)  ? xr[t+1] : 0.f;
    }
    size_t base = (((size_t)b*CO)*JJ + j)*TT + t;
    for (int o = 0; o < CO; o++) {
        const float* w = ws + o*9;
        float r = bs[o];
#pragma unroll
        for (int k = 0; k < 9; k++) r = fmaf(xv[k], w[k], r);
        g_xconv[base + (size_t)o*ROW] = fmaxf(r, 0.f);
    }
}

// ---------------- signature machinery ----------------
template<int N>
__device__ __forceinline__ void accum_proj(float* __restrict__ acc,
                                           const float* __restrict__ s,
                                           const float* __restrict__ A)
{
#pragma unroll
    for (int i = 0; i < N; i++) {
        float si = s[i];
        const float4* row = reinterpret_cast<const float4*>(A + i*CO);
#pragma unroll
        for (int o = 0; o < 16; o++) {
            float4 v = row[o];
            acc[4*o+0] = fmaf(si, v.x, acc[4*o+0]);
            acc[4*o+1] = fmaf(si, v.y, acc[4*o+1]);
            acc[4*o+2] = fmaf(si, v.z, acc[4*o+2]);
            acc[4*o+3] = fmaf(si, v.w, acc[4*o+3]);
        }
    }
}

__device__ __forceinline__ void chen_step(float S1[4], float S2[16], float S3[64], const float d[4])
{
    float B2[16];
#pragma unroll
    for (int i = 0; i < 4; i++)
#pragma unroll
        for (int jx = 0; jx < 4; jx++)
            B2[i*4+jx] = 0.5f * d[i] * d[jx];
    // S3 += B3 + S1 (x) B2 + S2 (x) d   (B3[ijk] = (d_i/3) * B2[jk])
#pragma unroll
    for (int i = 0; i < 4; i++) {
        float f = fmaf(d[i], (1.f/3.f), S1[i]);
#pragma unroll
        for (int jx = 0; jx < 4; jx++) {
            float s2 = S2[i*4+jx];
#pragma unroll
            for (int k = 0; k < 4; k++)
                S3[i*16+jx*4+k] += f * B2[jx*4+k] + s2 * d[k];
        }
    }
#pragma unroll
    for (int i = 0; i < 4; i++)
#pragma unroll
        for (int jx = 0; jx < 4; jx++)
            S2[i*4+jx] += B2[i*4+jx] + S1[i] * d[jx];
#pragma unroll
    for (int i = 0; i < 4; i++) S1[i] += d[i];
}

// path points p0,p1,p2 in R^3; augment with time (0, .5, 1); level-3 sig; acc += A^T sig
__device__ __forceinline__ void sig_accum(const float p0[3], const float p1[3], const float p2[3],
                                          const float* __restrict__ A, float acc[CO])
{
    float a[4], bv[4], cv[4];
    a[0] = 0.f; bv[0] = 0.5f; cv[0] = 0.5f;
#pragma unroll
    for (int c = 0; c < 3; c++) {
        a [c+1] = p0[c];
        bv[c+1] = p1[c] - p0[c];
        cv[c+1] = p2[c] - p1[c];
    }
    float S1[4], S2[16], S3[64];
#pragma unroll
    for (int i = 0; i < 4; i++) S1[i] = a[i];
#pragma unroll
    for (int i = 0; i < 4; i++)
#pragma unroll
        for (int jx = 0; jx < 4; jx++)
            S2[i*4+jx] = 0.5f * a[i] * a[jx];
#pragma unroll
    for (int i = 0; i < 4; i++)
#pragma unroll
        for (int jx = 0; jx < 4; jx++)
#pragma unroll
            for (int k = 0; k < 4; k++)
                S3[i*16+jx*4+k] = S2[i*4+jx] * a[k] * (1.f/3.f);
    chen_step(S1, S2, S3, bv);
    chen_step(S1, S2, S3, cv);
    accum_proj<4> (acc, S1, A);
    accum_proj<16>(acc, S2, A + 4*CO);
    accum_proj<64>(acc, S3, A + 20*CO);
}

// ---------------- spatial + temporal signatures, folded ps projection, relu ----------------
__global__ __launch_bounds__(256, 1) void k_sig(const float* __restrict__ x,
                                                const int* __restrict__ nbr)
{
    extern __shared__ float sh[];
    float* Asp = sh;                 // 5376
    float* Atp = sh + SIGC*CO;       // 5376
    float* psb = sh + 2*SIGC*CO;     // 64
    float* xs  = psb + 64;           // 4*3*256 rows: [slot][c][t]

    int b = blockIdx.x / JJ, j = blockIdx.x % JJ;
    int tid = threadIdx.x;

    for (int i = tid; i < SIGC*CO; i += 256) { Asp[i] = g_Asp[i]; Atp[i] = g_Atp[i]; }
    if (tid < CO) psb[tid] = g_psb[tid];

    int jo0 = j, jo1 = nbr[j*3+0], jo2 = nbr[j*3+1], jo3 = nbr[j*3+2];
    int jos[4] = {jo0, jo1, jo2, jo3};
#pragma unroll
    for (int s = 0; s < 4; s++)
#pragma unroll
        for (int c = 0; c < 3; c++)
            xs[(s*3+c)*TT + tid] = x[(((size_t)b*3 + c)*JJ + jos[s])*TT + tid];
    __syncthreads();

    int t = tid;
    float acc[CO];
#pragma unroll
    for (int o = 0; o < CO; o++) acc[o] = psb[o];

    { // temporal: window t-1..t+1 (edge-clamped) of joint j (slot 0)
        int tm = (t > 0) ? t-1 : 0;
        int tp = (t < TT-1) ? t+1 : TT-1;
        float p0[3], p1[3], p2[3];
#pragma unroll
        for (int c = 0; c < 3; c++) {
            p0[c] = xs[c*TT + tm];
            p1[c] = xs[c*TT + t ];
            p2[c] = xs[c*TT + tp];
        }
        sig_accum(p0, p1, p2, Atp, acc);
    }
    { // spatial: neighbors[j][0..2] at time t (slots 1..3)
        float p0[3], p1[3], p2[3];
#pragma unroll
        for (int c = 0; c < 3; c++) {
            p0[c] = xs[(3+c)*TT + t];
            p1[c] = xs[(6+c)*TT + t];
            p2[c] = xs[(9+c)*TT + t];
        }
        sig_accum(p0, p1, p2, Asp, acc);
    }

    size_t base = (((size_t)b*CO)*JJ + j)*TT + t;
#pragma unroll
    for (int o = 0; o < CO; o++)
        g_sig[base + (size_t)o*ROW] = fmaxf(acc[o], 0.f);
}

// ---------------- deterministic BN partial stats ----------------
// which==0: slots 0..127  (0..63 -> g_xconv ch, 64..127 -> g_sig ch)
// which==1: slots 128..191 (g_y ch)
__global__ void k_stats(int which)
{
    int p  = blockIdx.x;            // 0..15
    int ch = blockIdx.y;
    int tid = threadIdx.x;
    const float* src;
    int slot;
    if (which == 0) { src = (ch < 64) ? g_xconv : g_sig; slot = ch; }
    else            { src = g_y;                          slot = 128 + ch; }
    int c = ch & 63;

    double s = 0.0, q = 0.0;
    for (int bb = p*4; bb < p*4 + 4; bb++) {
        const float* ptr = src + ((size_t)bb*CO + c)*ROW;
        for (int r = tid; r < ROW; r += 256) {
            float v = ptr[r];
            s += v;
            q += (double)v * v;
        }
    }
    __shared__ double ss[256], sq[256];
    ss[tid] = s; sq[tid] = q;
    __syncthreads();
    for (int st = 128; st > 0; st >>= 1) {
        if (tid < st) { ss[tid] += ss[tid+st]; sq[tid] += sq[tid+st]; }
        __syncthreads();
    }
    if (tid == 0) {
        g_part[((size_t)slot*16 + p)*2 + 0] = ss[0];
        g_part[((size_t)slot*16 + p)*2 + 1] = sq[0];
    }
}

// ---------------- finalize BN(xconv), BN(sig); fold affines into fu weights ----------------
__global__ void k_fold2(const float* __restrict__ rg, const float* __restrict__ rb,
                        const float* __restrict__ pg, const float* __restrict__ pb,
                        const float* __restrict__ fuw, const float* __restrict__ fub)
{
    __shared__ float scale_sh[128], shift_sh[128];
    int tid = threadIdx.x;
    if (tid < 128) {
        double s = 0.0, q = 0.0;
        for (int p = 0; p < 16; p++) {
            s += g_part[((size_t)tid*16 + p)*2 + 0];
            q += g_part[((size_t)tid*16 + p)*2 + 1];
        }
        double mean = s / (double)NPIX;
        double var  = q / (double)NPIX - mean*mean;
        float gamma = (tid < 64) ? rg[tid] : pg[tid-64];
        float beta  = (tid < 64) ? rb[tid] : pb[tid-64];
        double sc = (double)gamma / sqrt(var + EPSV);
        scale_sh[tid] = (float)sc;
        shift_sh[tid] = (float)((double)beta - mean*sc);
    }
    __syncthreads();
    for (int idx = tid; idx < 128*CO; idx += blockDim.x) {
        int c = idx >> 6, o = idx & 63;
        g_fuwT[idx] = fuw[o*128 + c] * scale_sh[c];
    }
    if (tid < CO) {
        double bsum = fub[tid];
        for (int c = 0; c < 128; c++)
            bsum += (double)fuw[tid*128 + c] * (double)shift_sh[c];
        g_fub[tid] = (float)bsum;
    }
}

// ---------------- fu projection (BN folded) + relu ----------------
__device__ __forceinline__ void fma_row(float* __restrict__ acc, float v, const float* __restrict__ row)
{
    const float4* r4 = reinterpret_cast<const float4*>(row);
#pragma unroll
    for (int o = 0; o < 16; o++) {
        float4 w = r4[o];
        acc[4*o+0] = fmaf(v, w.x, acc[4*o+0]);
        acc[4*o+1] = fmaf(v, w.y, acc[4*o+1]);
        acc[4*o+2] = fmaf(v, w.z, acc[4*o+2]);
        acc[4*o+3] = fmaf(v, w.w, acc[4*o+3]);
    }
}

__global__ __launch_bounds__(256, 1) void k_fu()
{
    __shared__ float fw[128*CO];
    __shared__ float fb[CO];
    int b = blockIdx.x / JJ, j = blockIdx.x % JJ;
    int tid = threadIdx.x, t = tid;
    for (int i = tid; i < 128*CO; i += 256) fw[i] = g_fuwT[i];
    if (tid < CO) fb[tid] = g_fub[tid];
    __syncthreads();

    float acc[CO];
#pragma unroll
    for (int o = 0; o < CO; o++) acc[o] = fb[o];

    size_t base = (((size_t)b*CO)*JJ + j)*TT + t;
#pragma unroll 4
    for (int c = 0; c < CO; c++)
        fma_row(acc, g_xconv[base + (size_t)c*ROW], fw + c*CO);
#pragma unroll 4
    for (int c = 0; c < CO; c++)
        fma_row(acc, g_sig[base + (size_t)c*ROW], fw + (64 + c)*CO);

#pragma unroll
    for (int o = 0; o < CO; o++)
        g_y[base + (size_t)o*ROW] = fmaxf(acc[o], 0.f);
}

// ---------------- finalize BN(y) ----------------
__global__ void k_bny(const float* __restrict__ fg, const float* __restrict__ fbt)
{
    int tid = threadIdx.x;
    if (tid < CO) {
        double s = 0.0, q = 0.0;
        for (int p = 0; p < 16; p++) {
            s += g_part[((size_t)(128 + tid)*16 + p)*2 + 0];
            q += g_part[((size_t)(128 + tid)*16 + p)*2 + 1];
        }
        double mean = s / (double)NPIX;
        double var  = q / (double)NPIX - mean*mean;
        double sc = (double)fg[tid] / sqrt(var + EPSV);
        g_bny_scale[tid] = (float)sc;
        g_bny_shift[tid] = (float)((double)fbt[tid] - mean*sc);
    }
}

// ---------------- apply final BN, write output ----------------
__global__ void k_apply(float* __restrict__ out)
{
    int i = blockIdx.x*256 + threadIdx.x;   // float4 index, total 6,553,600
    float4 v = reinterpret_cast<const float4*>(g_y)[i];
    int c = (i / (ROW/4)) & 63;
    float sc = g_bny_scale[c], sf = g_bny_shift[c];
    float4 r;
    r.x = fmaf(v.x, sc, sf);
    r.y = fmaf(v.y, sc, sf);
    r.z = fmaf(v.z, sc, sf);
    r.w = fmaf(v.w, sc, sf);
    reinterpret_cast<float4*>(out)[i] = r;
}

// ---------------- launch ----------------
extern "C" void kernel_launch(void* const* d_in, const int* in_sizes, int n_in,
                              void* d_out, int out_size)
{
    const float* x        = (const float*)d_in[0];
    const float* conv_w   = (const float*)d_in[1];
    const float* conv_b   = (const float*)d_in[2];
    const float* raw_g    = (const float*)d_in[3];
    const float* raw_b    = (const float*)d_in[4];
    const float* sp_W     = (const float*)d_in[5];
    const float* sp_b     = (const float*)d_in[6];
    const float* tp_W     = (const float*)d_in[7];
    const float* tp_b     = (const float*)d_in[8];
    const float* ps_w     = (const float*)d_in[9];
    const float* ps_b     = (const float*)d_in[10];
    const float* ps_g     = (const float*)d_in[11];
    const float* ps_bt    = (const float*)d_in[12];
    const float* fu_w     = (const float*)d_in[13];
    const float* fu_b     = (const float*)d_in[14];
    const float* fu_g     = (const float*)d_in[15];
    const float* fu_bt    = (const float*)d_in[16];
    const int*   nbr      = (const int*)d_in[17];
    float* out            = (float*)d_out;

    const int sig_smem = (2*SIGC*CO + CO + 4*3*TT) * (int)sizeof(float);  // 55552 B
    cudaFuncSetAttribute(k_sig, cudaFuncAttributeMaxDynamicSharedMemorySize, sig_smem);

    k_fold1<<<1, 256>>>(sp_W, sp_b, tp_W, tp_b, ps_w, ps_b);
    k_conv <<<dim3(JJ, BB), 256>>>(x, conv_w, conv_b);
    k_sig  <<<BB*JJ, 256, sig_smem>>>(x, nbr);
    k_stats<<<dim3(16, 128), 256>>>(0);
    k_fold2<<<1, 128>>>(raw_g, raw_b, ps_g, ps_bt, fu_w, fu_b);
    k_fu   <<<BB*JJ, 256>>>();
    k_stats<<<dim3(16, 64), 256>>>(1);
    k_bny  <<<1, 64>>>(fu_g, fu_bt);
    k_apply<<<(BB*CO*ROW)/1024, 256>>>(out);
}

// round 5
// speedup vs baseline: 1.2532x; 1.2532x over previous
#include <cuda_runtime.h>
#include <math.h>

// Problem dims
#define BB   64
#define CC   3
#define JJ   25
#define TT   256
#define CO   64
#define ROW  (JJ*TT)            /* 6400 */
#define SIGC 84
#define NPIX (BB*JJ*TT)         /* 409600 per channel */
#define NBLK (BB*JJ)            /* 1600 producer blocks */
#define EPSV 1e-5

// ---------------- scratch (static device allocations: allowed) ----------------
__device__ float  g_xconv[(size_t)BB*CO*ROW];   // relu(conv), pre-BN
__device__ float  g_sig  [(size_t)BB*CO*ROW];   // relu(folded ps proj), pre-BN
__device__ float  g_y    [(size_t)BB*CO*ROW];   // relu(folded fu proj), pre-BN
__device__ float  g_Asp[SIGC*CO];
__device__ float  g_Atp[SIGC*CO];
__device__ float  g_psb[CO];
__device__ float  g_fuwT[128*CO];               // [c][o], BN folded in
__device__ float  g_fub[CO];
// per-(channel-slot, producer-block) fp32 partial {sum, sumsq}
__device__ float  g_partf[(size_t)192*NBLK*2];
__device__ double g_stat[192*2];                // finalized {sum, sumsq} per slot
__device__ float  g_bny_scale[CO];
__device__ float  g_bny_shift[CO];

// ---------------- in-block channel stats reduction ----------------
// v[64] = this thread's post-relu values for channels 0..63.
// Emits per-block partial sum/sumsq for slots [slotBase, slotBase+64).
__device__ __forceinline__ void emit_partials(const float* __restrict__ v,
                                              int slotBase, int blkId)
{
    __shared__ float red_s[8][64];
    __shared__ float red_q[8][64];
    int lane = threadIdx.x & 31, w = threadIdx.x >> 5;
#pragma unroll
    for (int o = 0; o < CO; o++) {
        float s = v[o];
        float q = s * s;
#pragma unroll
        for (int d = 16; d; d >>= 1) {
            s += __shfl_xor_sync(0xffffffffu, s, d);
            q += __shfl_xor_sync(0xffffffffu, q, d);
        }
        if (lane == 0) { red_s[w][o] = s; red_q[w][o] = q; }
    }
    __syncthreads();
    int tid = threadIdx.x;
    if (tid < 128) {
        int o = tid & 63;
        const float* src = (tid < 64) ? &red_s[0][o] : &red_q[0][o];
        float a = 0.f;
#pragma unroll
        for (int ww = 0; ww < 8; ww++) a += src[(size_t)ww*64];
        int slot = slotBase + o;
        g_partf[((size_t)slot*NBLK + blkId)*2 + (tid >= 64 ? 1 : 0)] = a;
    }
}

// ---------------- fold1: A_sp = sp_W @ ps_w_left^T, A_tp = tp_W @ ps_w_right^T ----------------
__global__ void k_fold1(const float* __restrict__ spW, const float* __restrict__ spb,
                        const float* __restrict__ tpW, const float* __restrict__ tpb,
                        const float* __restrict__ psw, const float* __restrict__ psb)
{
    int tid = threadIdx.x;
    for (int idx = tid; idx < SIGC*CO; idx += blockDim.x) {
        int i = idx / CO, o = idx % CO;
        float s1 = 0.f, s2 = 0.f;
        for (int c = 0; c < CO; c++) {
            s1 = fmaf(spW[i*CO + c], psw[o*128 + c],      s1);
            s2 = fmaf(tpW[i*CO + c], psw[o*128 + 64 + c], s2);
        }
        g_Asp[idx] = s1;
        g_Atp[idx] = s2;
    }
    if (tid < CO) {
        float bsum = psb[tid];
        for (int c = 0; c < CO; c++) {
            bsum = fmaf(spb[c], psw[tid*128 + c],      bsum);
            bsum = fmaf(tpb[c], psw[tid*128 + 64 + c], bsum);
        }
        g_psb[tid] = bsum;
    }
}

// ---------------- conv (1x3 along T, zero pad) + relu + stats ----------------
__global__ __launch_bounds__(256) void k_conv(const float* __restrict__ x,
                                              const float* __restrict__ cw,
                                              const float* __restrict__ cb)
{
    __shared__ float ws[CO*9];
    __shared__ float bs[CO];
    int j = blockIdx.x, b = blockIdx.y;
    int tid = threadIdx.x, t = tid;
    for (int i = tid; i < CO*9; i += 256) ws[i] = cw[i];
    if (tid < CO) bs[tid] = cb[tid];
    __syncthreads();

    float xv[9];
#pragma unroll
    for (int c = 0; c < 3; c++) {
        const float* xr = x + (((size_t)b*3 + c)*JJ + j)*TT;
        xv[c*3+0] = (t > 0)     ? xr[t-1] : 0.f;
        xv[c*3+1] = xr[t];
        xv[c*3+2] = (t < TT-1)  ? xr[t+1] : 0.f;
    }
    size_t base = (((size_t)b*CO)*JJ + j)*TT + t;
    float val[CO];
#pragma unroll
    for (int o = 0; o < CO; o++) {
        const float* w = ws + o*9;
        float r = bs[o];
#pragma unroll
        for (int k = 0; k < 9; k++) r = fmaf(xv[k], w[k], r);
        r = fmaxf(r, 0.f);
        val[o] = r;
        g_xconv[base + (size_t)o*ROW] = r;
    }
    emit_partials(val, 0, b*JJ + j);
}

// ---------------- signature machinery ----------------
template<int N>
__device__ __forceinline__ void accum_proj(float* __restrict__ acc,
                                           const float* __restrict__ s,
                                           const float* __restrict__ A)
{
#pragma unroll
    for (int i = 0; i < N; i++) {
        float si = s[i];
        const float4* row = reinterpret_cast<const float4*>(A + i*CO);
#pragma unroll
        for (int o = 0; o < 16; o++) {
            float4 v = row[o];
            acc[4*o+0] = fmaf(si, v.x, acc[4*o+0]);
            acc[4*o+1] = fmaf(si, v.y, acc[4*o+1]);
            acc[4*o+2] = fmaf(si, v.z, acc[4*o+2]);
            acc[4*o+3] = fmaf(si, v.w, acc[4*o+3]);
        }
    }
}

__device__ __forceinline__ void chen_step(float S1[4], float S2[16], float S3[64], const float d[4])
{
    float B2[16];
#pragma unroll
    for (int i = 0; i < 4; i++)
#pragma unroll
        for (int jx = 0; jx < 4; jx++)
            B2[i*4+jx] = 0.5f * d[i] * d[jx];
    // S3 += B3 + S1 (x) B2 + S2 (x) d   (B3[ijk] = (d_i/3) * B2[jk])
#pragma unroll
    for (int i = 0; i < 4; i++) {
        float f = fmaf(d[i], (1.f/3.f), S1[i]);
#pragma unroll
        for (int jx = 0; jx < 4; jx++) {
            float s2 = S2[i*4+jx];
#pragma unroll
            for (int k = 0; k < 4; k++)
                S3[i*16+jx*4+k] += f * B2[jx*4+k] + s2 * d[k];
        }
    }
#pragma unroll
    for (int i = 0; i < 4; i++)
#pragma unroll
        for (int jx = 0; jx < 4; jx++)
            S2[i*4+jx] += B2[i*4+jx] + S1[i] * d[jx];
#pragma unroll
    for (int i = 0; i < 4; i++) S1[i] += d[i];
}

// path points p0,p1,p2 in R^3; augment with time (0, .5, 1); level-3 sig; acc += A^T sig
__device__ __forceinline__ void sig_accum(const float p0[3], const float p1[3], const float p2[3],
                                          const float* __restrict__ A, float acc[CO])
{
    float a[4], bv[4], cv[4];
    a[0] = 0.f; bv[0] = 0.5f; cv[0] = 0.5f;
#pragma unroll
    for (int c = 0; c < 3; c++) {
        a [c+1] = p0[c];
        bv[c+1] = p1[c] - p0[c];
        cv[c+1] = p2[c] - p1[c];
    }
    float S1[4], S2[16], S3[64];
#pragma unroll
    for (int i = 0; i < 4; i++) S1[i] = a[i];
#pragma unroll
    for (int i = 0; i < 4; i++)
#pragma unroll
        for (int jx = 0; jx < 4; jx++)
            S2[i*4+jx] = 0.5f * a[i] * a[jx];
#pragma unroll
    for (int i = 0; i < 4; i++)
#pragma unroll
        for (int jx = 0; jx < 4; jx++)
#pragma unroll
            for (int k = 0; k < 4; k++)
                S3[i*16+jx*4+k] = S2[i*4+jx] * a[k] * (1.f/3.f);
    chen_step(S1, S2, S3, bv);
    chen_step(S1, S2, S3, cv);
    accum_proj<4> (acc, S1, A);
    accum_proj<16>(acc, S2, A + 4*CO);
    accum_proj<64>(acc, S3, A + 20*CO);
}

// ---------------- spatial + temporal signatures, folded ps projection, relu, stats ----------------
__global__ __launch_bounds__(256, 1) void k_sig(const float* __restrict__ x,
                                                const int* __restrict__ nbr)
{
    extern __shared__ float sh[];
    float* Asp = sh;                 // 5376
    float* Atp = sh + SIGC*CO;       // 5376
    float* psb = sh + 2*SIGC*CO;     // 64
    float* xs  = psb + 64;           // 4*3*256 rows: [slot][c][t]

    int b = blockIdx.x / JJ, j = blockIdx.x % JJ;
    int tid = threadIdx.x;

    for (int i = tid; i < SIGC*CO; i += 256) { Asp[i] = g_Asp[i]; Atp[i] = g_Atp[i]; }
    if (tid < CO) psb[tid] = g_psb[tid];

    int jo0 = j, jo1 = nbr[j*3+0], jo2 = nbr[j*3+1], jo3 = nbr[j*3+2];
    int jos[4] = {jo0, jo1, jo2, jo3};
#pragma unroll
    for (int s = 0; s < 4; s++)
#pragma unroll
        for (int c = 0; c < 3; c++)
            xs[(s*3+c)*TT + tid] = x[(((size_t)b*3 + c)*JJ + jos[s])*TT + tid];
    __syncthreads();

    int t = tid;
    float acc[CO];
#pragma unroll
    for (int o = 0; o < CO; o++) acc[o] = psb[o];

    { // temporal: window t-1..t+1 (edge-clamped) of joint j (slot 0)
        int tm = (t > 0) ? t-1 : 0;
        int tp = (t < TT-1) ? t+1 : TT-1;
        float p0[3], p1[3], p2[3];
#pragma unroll
        for (int c = 0; c < 3; c++) {
            p0[c] = xs[c*TT + tm];
            p1[c] = xs[c*TT + t ];
            p2[c] = xs[c*TT + tp];
        }
        sig_accum(p0, p1, p2, Atp, acc);
    }
    { // spatial: neighbors[j][0..2] at time t (slots 1..3)
        float p0[3], p1[3], p2[3];
#pragma unroll
        for (int c = 0; c < 3; c++) {
            p0[c] = xs[(3+c)*TT + t];
            p1[c] = xs[(6+c)*TT + t];
            p2[c] = xs[(9+c)*TT + t];
        }
        sig_accum(p0, p1, p2, Asp, acc);
    }

    size_t base = (((size_t)b*CO)*JJ + j)*TT + t;
#pragma unroll
    for (int o = 0; o < CO; o++) {
        float r = fmaxf(acc[o], 0.f);
        acc[o] = r;
        g_sig[base + (size_t)o*ROW] = r;
    }
    emit_partials(acc, 64, blockIdx.x);
}

// ---------------- combine per-block partials -> per-slot {sum, sumsq} (double) ----------------
__global__ void k_reduce(int slotBase)
{
    int slot = slotBase + blockIdx.x;
    int tid = threadIdx.x;
    const float2* p = reinterpret_cast<const float2*>(g_partf + (size_t)slot*NBLK*2);
    double s = 0.0, q = 0.0;
    for (int i = tid; i < NBLK; i += 256) {
        float2 v = p[i];
        s += (double)v.x;
        q += (double)v.y;
    }
    __shared__ double ss[256], sq[256];
    ss[tid] = s; sq[tid] = q;
    __syncthreads();
    for (int st = 128; st > 0; st >>= 1) {
        if (tid < st) { ss[tid] += ss[tid+st]; sq[tid] += sq[tid+st]; }
        __syncthreads();
    }
    if (tid == 0) {
        g_stat[slot*2 + 0] = ss[0];
        g_stat[slot*2 + 1] = sq[0];
    }
}

// ---------------- finalize BN(xconv), BN(sig); fold affines into fu weights ----------------
__global__ void k_fold2(const float* __restrict__ rg, const float* __restrict__ rb,
                        const float* __restrict__ pg, const float* __restrict__ pb,
                        const float* __restrict__ fuw, const float* __restrict__ fub)
{
    __shared__ float scale_sh[128], shift_sh[128];
    int tid = threadIdx.x;
    if (tid < 128) {
        double s = g_stat[tid*2 + 0];
        double q = g_stat[tid*2 + 1];
        double mean = s / (double)NPIX;
        double var  = q / (double)NPIX - mean*mean;
        float gamma = (tid < 64) ? rg[tid] : pg[tid-64];
        float beta  = (tid < 64) ? rb[tid] : pb[tid-64];
        double sc = (double)gamma / sqrt(var + EPSV);
        scale_sh[tid] = (float)sc;
        shift_sh[tid] = (float)((double)beta - mean*sc);
    }
    __syncthreads();
    for (int idx = tid; idx < 128*CO; idx += blockDim.x) {
        int c = idx >> 6, o = idx & 63;
        g_fuwT[idx] = fuw[o*128 + c] * scale_sh[c];
    }
    if (tid < CO) {
        double bsum = fub[tid];
        for (int c = 0; c < 128; c++)
            bsum += (double)fuw[tid*128 + c] * (double)shift_sh[c];
        g_fub[tid] = (float)bsum;
    }
}

// ---------------- fu projection (BN folded) + relu + stats ----------------
__device__ __forceinline__ void fma_row(float* __restrict__ acc, float v, const float* __restrict__ row)
{
    const float4* r4 = reinterpret_cast<const float4*>(row);
#pragma unroll
    for (int o = 0; o < 16; o++) {
        float4 w = r4[o];
        acc[4*o+0] = fmaf(v, w.x, acc[4*o+0]);
        acc[4*o+1] = fmaf(v, w.y, acc[4*o+1]);
        acc[4*o+2] = fmaf(v, w.z, acc[4*o+2]);
        acc[4*o+3] = fmaf(v, w.w, acc[4*o+3]);
    }
}

__global__ __launch_bounds__(256, 1) void k_fu()
{
    __shared__ float fw[128*CO];
    __shared__ float fb[CO];
    int b = blockIdx.x / JJ, j = blockIdx.x % JJ;
    int tid = threadIdx.x, t = tid;
    for (int i = tid; i < 128*CO; i += 256) fw[i] = g_fuwT[i];
    if (tid < CO) fb[tid] = g_fub[tid];
    __syncthreads();

    float acc[CO];
#pragma unroll
    for (int o = 0; o < CO; o++) acc[o] = fb[o];

    size_t base = (((size_t)b*CO)*JJ + j)*TT + t;
#pragma unroll 8
    for (int c = 0; c < CO; c++)
        fma_row(acc, g_xconv[base + (size_t)c*ROW], fw + c*CO);
#pragma unroll 8
    for (int c = 0; c < CO; c++)
        fma_row(acc, g_sig[base + (size_t)c*ROW], fw + (64 + c)*CO);

#pragma unroll
    for (int o = 0; o < CO; o++) {
        float r = fmaxf(acc[o], 0.f);
        acc[o] = r;
        g_y[base + (size_t)o*ROW] = r;
    }
    emit_partials(acc, 128, blockIdx.x);
}

// ---------------- finalize BN(y) ----------------
__global__ void k_bny(const float* __restrict__ fg, const float* __restrict__ fbt)
{
    int tid = threadIdx.x;
    if (tid < CO) {
        double s = g_stat[(128 + tid)*2 + 0];
        double q = g_stat[(128 + tid)*2 + 1];
        double mean = s / (double)NPIX;
        double var  = q / (double)NPIX - mean*mean;
        double sc = (double)fg[tid] / sqrt(var + EPSV);
        g_bny_scale[tid] = (float)sc;
        g_bny_shift[tid] = (float)((double)fbt[tid] - mean*sc);
    }
}

// ---------------- apply final BN, write output ----------------
__global__ void k_apply(float* __restrict__ out)
{
    int i = blockIdx.x*256 + threadIdx.x;   // float4 index, total 6,553,600
    float4 v = reinterpret_cast<const float4*>(g_y)[i];
    int c = (i / (ROW/4)) & 63;
    float sc = g_bny_scale[c], sf = g_bny_shift[c];
    float4 r;
    r.x = fmaf(v.x, sc, sf);
    r.y = fmaf(v.y, sc, sf);
    r.z = fmaf(v.z, sc, sf);
    r.w = fmaf(v.w, sc, sf);
    reinterpret_cast<float4*>(out)[i] = r;
}

// ---------------- launch ----------------
extern "C" void kernel_launch(void* const* d_in, const int* in_sizes, int n_in,
                              void* d_out, int out_size)
{
    const float* x        = (const float*)d_in[0];
    const float* conv_w   = (const float*)d_in[1];
    const float* conv_b   = (const float*)d_in[2];
    const float* raw_g    = (const float*)d_in[3];
    const float* raw_b    = (const float*)d_in[4];
    const float* sp_W     = (const float*)d_in[5];
    const float* sp_b     = (const float*)d_in[6];
    const float* tp_W     = (const float*)d_in[7];
    const float* tp_b     = (const float*)d_in[8];
    const float* ps_w     = (const float*)d_in[9];
    const float* ps_b     = (const float*)d_in[10];
    const float* ps_g     = (const float*)d_in[11];
    const float* ps_bt    = (const float*)d_in[12];
    const float* fu_w     = (const float*)d_in[13];
    const float* fu_b     = (const float*)d_in[14];
    const float* fu_g     = (const float*)d_in[15];
    const float* fu_bt    = (const float*)d_in[16];
    const int*   nbr      = (const int*)d_in[17];
    float* out            = (float*)d_out;

    const int sig_smem = (2*SIGC*CO + CO + 4*3*TT) * (int)sizeof(float);  // 55552 B
    cudaFuncSetAttribute(k_sig, cudaFuncAttributeMaxDynamicSharedMemorySize, sig_smem);

    k_fold1 <<<1, 256>>>(sp_W, sp_b, tp_W, tp_b, ps_w, ps_b);
    k_conv  <<<dim3(JJ, BB), 256>>>(x, conv_w, conv_b);
    k_sig   <<<BB*JJ, 256, sig_smem>>>(x, nbr);
    k_reduce<<<128, 256>>>(0);
    k_fold2 <<<1, 128>>>(raw_g, raw_b, ps_g, ps_bt, fu_w, fu_b);
    k_fu    <<<BB*JJ, 256>>>();
    k_reduce<<<64, 256>>>(128);
    k_bny   <<<1, 64>>>(fu_g, fu_bt);
    k_apply <<<(BB*CO*ROW)/1024, 256>>>(out);
}

// round 7
// speedup vs baseline: 1.7393x; 1.3879x over previous
#include <cuda_runtime.h>
#include <math.h>
#include <stdint.h>

// Problem dims
#define BB   64
#define JJ   25
#define TT   256
#define CO   64
#define ROW  (JJ*TT)            /* 6400 */
#define SIGC 84
#define NPIX (BB*JJ*TT)         /* 409600 per channel */
#define NBLK2 3200              /* partial-stats stride (max producer blocks) */
#define EPSV 1e-5

#define KS   168                /* sig GEMM K: 84 temporal + 84 spatial (=8*21) */
#define KF   128                /* fusion GEMM K */
#define STS  169                /* odd fp32 word stride (conflict-free) */
#define STF  129

// ---------------- scratch (static device allocations: allowed) ----------------
__device__ float  g_xconv[(size_t)BB*CO*ROW];
__device__ float  g_sig  [(size_t)BB*CO*ROW];
__device__ float  g_y    [(size_t)BB*CO*ROW];
__device__ float  g_psb[CO];
__device__ float  g_fub[CO];
__device__ float  g_Bsig[CO*KS];     // [o][k] plain row-major
__device__ float  g_Bfu [CO*KF];     // [o][k], BN folded
__device__ float  g_partf[(size_t)192*NBLK2*2];
__device__ double g_stat[192*2];
__device__ float  g_bny_scale[CO];
__device__ float  g_bny_shift[CO];

// ---------------- tf32 mma helpers (standard PTX, sm_80+) ----------------
__device__ __forceinline__ void split_tf32(float f, uint32_t& hi, uint32_t& lo) {
    asm("cvt.rna.tf32.f32 %0, %1;" : "=r"(hi) : "f"(f));
    float r = f - __uint_as_float(hi);
    asm("cvt.rna.tf32.f32 %0, %1;" : "=r"(lo) : "f"(r));
}
__device__ __forceinline__ void mma_tf32(float* c, const uint32_t* a, uint32_t b0, uint32_t b1) {
    asm volatile("mma.sync.aligned.m16n8k8.row.col.f32.tf32.tf32.f32 "
                 "{%0,%1,%2,%3}, {%4,%5,%6,%7}, {%8,%9}, {%0,%1,%2,%3};"
                 : "+f"(c[0]), "+f"(c[1]), "+f"(c[2]), "+f"(c[3])
                 : "r"(a[0]), "r"(a[1]), "r"(a[2]), "r"(a[3]), "r"(b0), "r"(b1));
}

// ---------------- 8-warp producer stats (k_conv) ----------------
__device__ __forceinline__ void emit8(const float* v, int slotBase, int blkId) {
    __shared__ float rs[8][64], rq[8][64];
    int lane = threadIdx.x & 31, w = threadIdx.x >> 5;
#pragma unroll
    for (int o = 0; o < CO; o++) {
        float s = v[o], q = s * s;
#pragma unroll
        for (int d = 16; d; d >>= 1) {
            s += __shfl_xor_sync(0xffffffffu, s, d);
            q += __shfl_xor_sync(0xffffffffu, q, d);
        }
        if (lane == 0) { rs[w][o] = s; rq[w][o] = q; }
    }
    __syncthreads();
    int tid = threadIdx.x;
    if (tid < 128) {
        int o = tid & 63;
        float a = 0.f;
        if (tid < 64) {
#pragma unroll
            for (int ww = 0; ww < 8; ww++) a += rs[ww][o];
        } else {
#pragma unroll
            for (int ww = 0; ww < 8; ww++) a += rq[ww][o];
        }
        g_partf[((size_t)(slotBase + o) * NBLK2 + blkId) * 2 + (tid >= 64 ? 1 : 0)] = a;
    }
}

// ---------------- fold1: sig->ps weights, combined [o][k] fp32 ----------------
__global__ void k_fold1(const float* __restrict__ spW, const float* __restrict__ spb,
                        const float* __restrict__ tpW, const float* __restrict__ tpb,
                        const float* __restrict__ psw, const float* __restrict__ psb)
{
    int tid = threadIdx.x;
    for (int idx = tid; idx < CO * KS; idx += blockDim.x) {
        int o = idx / KS, k = idx % KS;
        float w = 0.f;
        if (k < SIGC) {               // temporal features (right half of psw)
            for (int c = 0; c < CO; c++) w = fmaf(tpW[k * CO + c], psw[o * 128 + 64 + c], w);
        } else {                      // spatial features (left half)
            int kk = k - SIGC;
            for (int c = 0; c < CO; c++) w = fmaf(spW[kk * CO + c], psw[o * 128 + c], w);
        }
        g_Bsig[idx] = w;
    }
    if (tid < CO) {
        float bsum = psb[tid];
        for (int c = 0; c < CO; c++) {
            bsum = fmaf(spb[c], psw[tid * 128 + c],      bsum);
            bsum = fmaf(tpb[c], psw[tid * 128 + 64 + c], bsum);
        }
        g_psb[tid] = bsum;
    }
}

// ---------------- conv (1x3 along T, zero pad) + relu + stats ----------------
__global__ __launch_bounds__(256) void k_conv(const float* __restrict__ x,
                                              const float* __restrict__ cw,
                                              const float* __restrict__ cb)
{
    __shared__ float ws[CO * 9];
    __shared__ float bs[CO];
    int j = blockIdx.x, b = blockIdx.y;
    int tid = threadIdx.x, t = tid;
    for (int i = tid; i < CO * 9; i += 256) ws[i] = cw[i];
    if (tid < CO) bs[tid] = cb[tid];
    __syncthreads();

    float xv[9];
#pragma unroll
    for (int c = 0; c < 3; c++) {
        const float* xr = x + (((size_t)b * 3 + c) * JJ + j) * TT;
        xv[c * 3 + 0] = (t > 0)      ? xr[t - 1] : 0.f;
        xv[c * 3 + 1] = xr[t];
        xv[c * 3 + 2] = (t < TT - 1) ? xr[t + 1] : 0.f;
    }
    size_t base = (((size_t)b * CO) * JJ + j) * TT + t;
    float val[CO];
#pragma unroll
    for (int o = 0; o < CO; o++) {
        const float* w = ws + o * 9;
        float r = bs[o];
#pragma unroll
        for (int k = 0; k < 9; k++) r = fmaf(xv[k], w[k], r);
        r = fmaxf(r, 0.f);
        val[o] = r;
        g_xconv[base + (size_t)o * ROW] = r;
    }
    emit8(val, 0, b * JJ + j);
}

// ---------------- signature features ----------------
__device__ __forceinline__ void chen_step(float S1[4], float S2[16], float S3[64], const float d[4])
{
    float B2[16];
#pragma unroll
    for (int i = 0; i < 4; i++)
#pragma unroll
        for (int jx = 0; jx < 4; jx++)
            B2[i * 4 + jx] = 0.5f * d[i] * d[jx];
#pragma unroll
    for (int i = 0; i < 4; i++) {
        float f = fmaf(d[i], (1.f / 3.f), S1[i]);
#pragma unroll
        for (int jx = 0; jx < 4; jx++) {
            float s2 = S2[i * 4 + jx];
#pragma unroll
            for (int k = 0; k < 4; k++)
                S3[i * 16 + jx * 4 + k] += f * B2[jx * 4 + k] + s2 * d[k];
        }
    }
#pragma unroll
    for (int i = 0; i < 4; i++)
#pragma unroll
        for (int jx = 0; jx < 4; jx++)
            S2[i * 4 + jx] += B2[i * 4 + jx] + S1[i] * d[jx];
#pragma unroll
    for (int i = 0; i < 4; i++) S1[i] += d[i];
}

// level-3 signature of [p0,p1,p2] time-augmented; write 84 features to arow[]
__device__ __forceinline__ void sig_feat(const float p0[3], const float p1[3], const float p2[3],
                                         float* __restrict__ arow)
{
    float a[4], bv[4], cv[4];
    a[0] = 0.f; bv[0] = 0.5f; cv[0] = 0.5f;
#pragma unroll
    for (int c = 0; c < 3; c++) {
        a [c + 1] = p0[c];
        bv[c + 1] = p1[c] - p0[c];
        cv[c + 1] = p2[c] - p1[c];
    }
    float S1[4], S2[16], S3[64];
#pragma unroll
    for (int i = 0; i < 4; i++) S1[i] = a[i];
#pragma unroll
    for (int i = 0; i < 4; i++)
#pragma unroll
        for (int jx = 0; jx < 4; jx++)
            S2[i * 4 + jx] = 0.5f * a[i] * a[jx];
#pragma unroll
    for (int i = 0; i < 4; i++)
#pragma unroll
        for (int jx = 0; jx < 4; jx++)
#pragma unroll
            for (int k = 0; k < 4; k++)
                S3[i * 16 + jx * 4 + k] = S2[i * 4 + jx] * a[k] * (1.f / 3.f);
    chen_step(S1, S2, S3, bv);
    chen_step(S1, S2, S3, cv);
#pragma unroll
    for (int i = 0; i < 4; i++)  arow[i]      = S1[i];
#pragma unroll
    for (int i = 0; i < 16; i++) arow[4 + i]  = S2[i];
#pragma unroll
    for (int i = 0; i < 64; i++) arow[20 + i] = S3[i];
}

// ---------------- shared epilogue: stage C, coalesced write + stats ----------------
// Csh: [128][65] fp32; writes dst[o*ROW + tbase + r] and partials for slotBase+o.
__device__ __forceinline__ void epilogue(float* __restrict__ Csh, const float C[8][4],
                                         const float* __restrict__ bias,
                                         float* __restrict__ dst, size_t bofs, int tbase,
                                         int slotBase, int blkId, int wid, int lane)
{
    int qr = lane >> 2, ql = lane & 3;
    int m0 = 16 * wid + qr;
#pragma unroll
    for (int nt = 0; nt < 8; nt++) {
        int n0 = nt * 8 + 2 * ql;
        Csh[m0 * 65 + n0]           = fmaxf(C[nt][0] + bias[n0],     0.f);
        Csh[m0 * 65 + n0 + 1]       = fmaxf(C[nt][1] + bias[n0 + 1], 0.f);
        Csh[(m0 + 8) * 65 + n0]     = fmaxf(C[nt][2] + bias[n0],     0.f);
        Csh[(m0 + 8) * 65 + n0 + 1] = fmaxf(C[nt][3] + bias[n0 + 1], 0.f);
    }
    __syncthreads();
    int tid = threadIdx.x;
    int o = tid >> 2, rc = (tid & 3) * 32;
    float* gp = dst + bofs + (size_t)o * ROW + tbase + rc;
    float s = 0.f, q = 0.f;
#pragma unroll
    for (int r = 0; r < 32; r += 4) {
        float v0 = Csh[(rc + r + 0) * 65 + o];
        float v1 = Csh[(rc + r + 1) * 65 + o];
        float v2 = Csh[(rc + r + 2) * 65 + o];
        float v3 = Csh[(rc + r + 3) * 65 + o];
        s += v0 + v1 + v2 + v3;
        q += v0 * v0 + v1 * v1 + v2 * v2 + v3 * v3;
        float4 w = make_float4(v0, v1, v2, v3);
        *(float4*)(gp + r) = w;
    }
    s += __shfl_xor_sync(0xffffffffu, s, 1);
    q += __shfl_xor_sync(0xffffffffu, q, 1);
    s += __shfl_xor_sync(0xffffffffu, s, 2);
    q += __shfl_xor_sync(0xffffffffu, q, 2);
    if ((tid & 3) == 0) {
        g_partf[((size_t)(slotBase + o) * NBLK2 + blkId) * 2 + 0] = s;
        g_partf[((size_t)(slotBase + o) * NBLK2 + blkId) * 2 + 1] = q;
    }
}

// ---------------- k_sig: features + tf32-split MMA (M=128,N=64,K=168) ----------------
#define SIG_SMEM ((CO*STS + 64 + 128*STS) * (int)sizeof(float))

__global__ __launch_bounds__(256, 1) void k_sig(const float* __restrict__ x,
                                                const int* __restrict__ nbr)
{
    extern __shared__ float sm[];
    float* Bs     = sm;                 // [64][STS]
    float* psb_sh = sm + CO * STS;      // [64]
    float* As     = psb_sh + 64;        // [128][STS], aliased as Csh later
    float* Csh    = As;

    int tid = threadIdx.x, wid = tid >> 5, lane = tid & 31;
    int bi = blockIdx.x;
    int h = bi & 1, j = (bi >> 1) % JJ, b = (bi >> 1) / JJ;

    for (int i = tid; i < CO * KS; i += 256) {
        int o = i / KS, k = i % KS;
        Bs[o * STS + k] = g_Bsig[i];
    }
    if (tid < CO) psb_sh[tid] = g_psb[tid];

    int row = tid & 127;
    int t = h * 128 + row;
    if (tid < 128) {
        int tm = (t > 0) ? t - 1 : 0;
        int tp = (t < TT - 1) ? t + 1 : TT - 1;
        float p0[3], p1[3], p2[3];
#pragma unroll
        for (int c = 0; c < 3; c++) {
            const float* xr = x + (((size_t)b * 3 + c) * JJ + j) * TT;
            p0[c] = xr[tm]; p1[c] = xr[t]; p2[c] = xr[tp];
        }
        sig_feat(p0, p1, p2, As + row * STS);
    } else {
        int n0 = nbr[j * 3 + 0], n1 = nbr[j * 3 + 1], n2 = nbr[j * 3 + 2];
        float p0[3], p1[3], p2[3];
#pragma unroll
        for (int c = 0; c < 3; c++) {
            p0[c] = x[(((size_t)b * 3 + c) * JJ + n0) * TT + t];
            p1[c] = x[(((size_t)b * 3 + c) * JJ + n1) * TT + t];
            p2[c] = x[(((size_t)b * 3 + c) * JJ + n2) * TT + t];
        }
        sig_feat(p0, p1, p2, As + row * STS + SIGC);
    }
    __syncthreads();

    float C[8][4];
#pragma unroll
    for (int nt = 0; nt < 8; nt++)
#pragma unroll
        for (int i = 0; i < 4; i++) C[nt][i] = 0.f;

    int qr = lane >> 2, ql = lane & 3;
    const float* aP0 = As + (16 * wid + qr) * STS;
    const float* aP1 = aP0 + 8 * STS;
    const float* bP0 = Bs + qr * STS;

    for (int ks = 0; ks < KS / 8; ks++) {
        int k0 = ks * 8 + ql;
        uint32_t ah[4], al[4];
        split_tf32(aP0[k0],     ah[0], al[0]);
        split_tf32(aP1[k0],     ah[1], al[1]);
        split_tf32(aP0[k0 + 4], ah[2], al[2]);
        split_tf32(aP1[k0 + 4], ah[3], al[3]);
        const float* bp = bP0 + k0;
#pragma unroll
        for (int nt = 0; nt < 8; nt++) {
            uint32_t bh0, bl0, bh1, bl1;
            split_tf32(bp[nt * 8 * STS],     bh0, bl0);
            split_tf32(bp[nt * 8 * STS + 4], bh1, bl1);
            mma_tf32(C[nt], ah, bh0, bh1);
            mma_tf32(C[nt], ah, bl0, bl1);
            mma_tf32(C[nt], al, bh0, bh1);
        }
    }
    __syncthreads();

    size_t bofs = ((size_t)b * CO) * ROW + j * TT;
    epilogue(Csh, C, psb_sh, g_sig, bofs, h * 128, 64, bi, wid, lane);
}

// ---------------- combine per-block partials -> per-slot {sum, sumsq} (double) ----------------
__global__ void k_reduce(int slotBase)
{
    int slot = slotBase + blockIdx.x;
    int nblk = (slot < 64) ? (BB * JJ) : NBLK2;
    int tid = threadIdx.x;
    const float2* p = reinterpret_cast<const float2*>(g_partf + (size_t)slot * NBLK2 * 2);
    double s = 0.0, q = 0.0;
    for (int i = tid; i < nblk; i += 256) {
        float2 v = p[i];
        s += (double)v.x;
        q += (double)v.y;
    }
    __shared__ double ss[256], sq[256];
    ss[tid] = s; sq[tid] = q;
    __syncthreads();
    for (int st = 128; st > 0; st >>= 1) {
        if (tid < st) { ss[tid] += ss[tid + st]; sq[tid] += sq[tid + st]; }
        __syncthreads();
    }
    if (tid == 0) {
        g_stat[slot * 2 + 0] = ss[0];
        g_stat[slot * 2 + 1] = sq[0];
    }
}

// ---------------- fold2: BN affines folded into fu weights [o][k] ----------------
__global__ void k_fold2(const float* __restrict__ rg, const float* __restrict__ rb,
                        const float* __restrict__ pg, const float* __restrict__ pb,
                        const float* __restrict__ fuw, const float* __restrict__ fub)
{
    __shared__ float scale_sh[128], shift_sh[128];
    int tid = threadIdx.x;
    if (tid < 128) {
        double s = g_stat[tid * 2 + 0];
        double q = g_stat[tid * 2 + 1];
        double mean = s / (double)NPIX;
        double var  = q / (double)NPIX - mean * mean;
        float gamma = (tid < 64) ? rg[tid] : pg[tid - 64];
        float beta  = (tid < 64) ? rb[tid] : pb[tid - 64];
        double sc = (double)gamma / sqrt(var + EPSV);
        scale_sh[tid] = (float)sc;
        shift_sh[tid] = (float)((double)beta - mean * sc);
    }
    __syncthreads();
    for (int idx = tid; idx < CO * KF; idx += blockDim.x) {
        int o = idx / KF, c = idx % KF;
        g_Bfu[idx] = fuw[o * 128 + c] * scale_sh[c];
    }
    if (tid < CO) {
        double bsum = fub[tid];
        for (int c = 0; c < 128; c++)
            bsum += (double)fuw[tid * 128 + c] * (double)shift_sh[c];
        g_fub[tid] = (float)bsum;
    }
}

// ---------------- k_fu: tf32-split fusion GEMM (M=128,N=64,K=128) ----------------
#define FU_SMEM ((CO*STF + 64 + 128*STF) * (int)sizeof(float))

__global__ __launch_bounds__(256, 1) void k_fu()
{
    extern __shared__ float sm[];
    float* Bf    = sm;                  // [64][STF]
    float* fb_sh = sm + CO * STF;       // [64]
    float* Af    = fb_sh + 64;          // [128][STF], aliased as Csh
    float* Csh   = Af;

    int tid = threadIdx.x, wid = tid >> 5, lane = tid & 31;
    int bi = blockIdx.x;
    int h = bi & 1, j = (bi >> 1) % JJ, b = (bi >> 1) / JJ;

    for (int i = tid; i < CO * KF; i += 256) {
        int o = i / KF, k = i % KF;
        Bf[o * STF + k] = g_Bfu[i];
    }
    if (tid < CO) fb_sh[tid] = g_fub[tid];

    int row = tid & 127;
    int t = h * 128 + row;
    const float* src = (tid < 128) ? g_xconv : g_sig;
    float* arow = Af + row * STF + ((tid < 128) ? 0 : 64);
    size_t sb2 = ((size_t)b * CO) * ROW + j * TT + t;
#pragma unroll 8
    for (int c = 0; c < CO; c++)
        arow[c] = src[sb2 + (size_t)c * ROW];
    __syncthreads();

    float C[8][4];
#pragma unroll
    for (int nt = 0; nt < 8; nt++)
#pragma unroll
        for (int i = 0; i < 4; i++) C[nt][i] = 0.f;

    int qr = lane >> 2, ql = lane & 3;
    const float* aP0 = Af + (16 * wid + qr) * STF;
    const float* aP1 = aP0 + 8 * STF;
    const float* bP0 = Bf + qr * STF;

    for (int ks = 0; ks < KF / 8; ks++) {
        int k0 = ks * 8 + ql;
        uint32_t ah[4], al[4];
        split_tf32(aP0[k0],     ah[0], al[0]);
        split_tf32(aP1[k0],     ah[1], al[1]);
        split_tf32(aP0[k0 + 4], ah[2], al[2]);
        split_tf32(aP1[k0 + 4], ah[3], al[3]);
        const float* bp = bP0 + k0;
#pragma unroll
        for (int nt = 0; nt < 8; nt++) {
            uint32_t bh0, bl0, bh1, bl1;
            split_tf32(bp[nt * 8 * STF],     bh0, bl0);
            split_tf32(bp[nt * 8 * STF + 4], bh1, bl1);
            mma_tf32(C[nt], ah, bh0, bh1);
            mma_tf32(C[nt], ah, bl0, bl1);
            mma_tf32(C[nt], al, bh0, bh1);
        }
    }
    __syncthreads();

    size_t bofs = ((size_t)b * CO) * ROW + j * TT;
    epilogue(Csh, C, fb_sh, g_y, bofs, h * 128, 128, bi, wid, lane);
}

// ---------------- finalize BN(y) ----------------
__global__ void k_bny(const float* __restrict__ fg, const float* __restrict__ fbt)
{
    int tid = threadIdx.x;
    if (tid < CO) {
        double s = g_stat[(128 + tid) * 2 + 0];
        double q = g_stat[(128 + tid) * 2 + 1];
        double mean = s / (double)NPIX;
        double var  = q / (double)NPIX - mean * mean;
        double sc = (double)fg[tid] / sqrt(var + EPSV);
        g_bny_scale[tid] = (float)sc;
        g_bny_shift[tid] = (float)((double)fbt[tid] - mean * sc);
    }
}

// ---------------- apply final BN, write output ----------------
__global__ void k_apply(float* __restrict__ out)
{
    int i = blockIdx.x * 256 + threadIdx.x;   // float4 index
    float4 v = reinterpret_cast<const float4*>(g_y)[i];
    int c = (i / (ROW / 4)) & 63;
    float sc = g_bny_scale[c], sf = g_bny_shift[c];
    float4 r;
    r.x = fmaf(v.x, sc, sf);
    r.y = fmaf(v.y, sc, sf);
    r.z = fmaf(v.z, sc, sf);
    r.w = fmaf(v.w, sc, sf);
    reinterpret_cast<float4*>(out)[i] = r;
}

// ---------------- launch ----------------
extern "C" void kernel_launch(void* const* d_in, const int* in_sizes, int n_in,
                              void* d_out, int out_size)
{
    const float* x      = (const float*)d_in[0];
    const float* conv_w = (const float*)d_in[1];
    const float* conv_b = (const float*)d_in[2];
    const float* raw_g  = (const float*)d_in[3];
    const float* raw_b  = (const float*)d_in[4];
    const float* sp_W   = (const float*)d_in[5];
    const float* sp_b   = (const float*)d_in[6];
    const float* tp_W   = (const float*)d_in[7];
    const float* tp_b   = (const float*)d_in[8];
    const float* ps_w   = (const float*)d_in[9];
    const float* ps_b   = (const float*)d_in[10];
    const float* ps_g   = (const float*)d_in[11];
    const float* ps_bt  = (const float*)d_in[12];
    const float* fu_w   = (const float*)d_in[13];
    const float* fu_b   = (const float*)d_in[14];
    const float* fu_g   = (const float*)d_in[15];
    const float* fu_bt  = (const float*)d_in[16];
    const int*   nbr    = (const int*)d_in[17];
    float* out          = (float*)d_out;

    cudaFuncSetAttribute(k_sig, cudaFuncAttributeMaxDynamicSharedMemorySize, SIG_SMEM);
    cudaFuncSetAttribute(k_fu,  cudaFuncAttributeMaxDynamicSharedMemorySize, FU_SMEM);

    k_fold1 <<<1, 256>>>(sp_W, sp_b, tp_W, tp_b, ps_w, ps_b);
    k_conv  <<<dim3(JJ, BB), 256>>>(x, conv_w, conv_b);
    k_sig   <<<BB * JJ * 2, 256, SIG_SMEM>>>(x, nbr);
    k_reduce<<<128, 256>>>(0);
    k_fold2 <<<1, 256>>>(raw_g, raw_b, ps_g, ps_bt, fu_w, fu_b);
    k_fu    <<<BB * JJ * 2, 256, FU_SMEM>>>();
    k_reduce<<<64, 256>>>(128);
    k_bny   <<<1, 64>>>(fu_g, fu_bt);
    k_apply <<<(BB * CO * ROW) / 1024, 256>>>(out);
}

// round 8
// speedup vs baseline: 1.8029x; 1.0366x over previous
#include <cuda_runtime.h>
#include <math.h>
#include <stdint.h>

// Problem dims
#define BB   64
#define JJ   25
#define TT   256
#define CO   64
#define ROW  (JJ*TT)            /* 6400 */
#define SIGC 84
#define NPIX (BB*JJ*TT)         /* 409600 per channel */
#define NBLK2 3200              /* partial-stats stride */
#define EPSV 1e-5

#define KS   168                /* sig GEMM K */
#define KF   128                /* fusion GEMM K */
#define STS  169                /* word stride, 169 % 32 == 9 (conflict-free) */
#define STF  137                /* word stride, 137 % 32 == 9 */

// ---------------- scratch (static device allocations: allowed) ----------------
__device__ float    g_sig[(size_t)BB*CO*ROW];
__device__ float    g_y  [(size_t)BB*CO*ROW];
__device__ float    g_psb[CO];
__device__ float    g_fub[CO];
__device__ uint32_t g_Bsig_hi[CO*KS];   // tf32 bit patterns, [o][k]
__device__ uint32_t g_Bsig_lo[CO*KS];
__device__ uint32_t g_Bfu_hi[CO*KF];    // BN folded
__device__ uint32_t g_Bfu_lo[CO*KF];
__device__ float    g_partf[(size_t)192*NBLK2*2];
__device__ double   g_stat[192*2];
__device__ float    g_bny_scale[CO];
__device__ float    g_bny_shift[CO];

// ---------------- tf32 mma helpers ----------------
__device__ __forceinline__ void split_tf32(float f, uint32_t& hi, uint32_t& lo) {
    asm("cvt.rna.tf32.f32 %0, %1;" : "=r"(hi) : "f"(f));
    float r = f - __uint_as_float(hi);
    asm("cvt.rna.tf32.f32 %0, %1;" : "=r"(lo) : "f"(r));
}
__device__ __forceinline__ void mma_tf32(float* c, const uint32_t* a, uint32_t b0, uint32_t b1) {
    asm volatile("mma.sync.aligned.m16n8k8.row.col.f32.tf32.tf32.f32 "
                 "{%0,%1,%2,%3}, {%4,%5,%6,%7}, {%8,%9}, {%0,%1,%2,%3};"
                 : "+f"(c[0]), "+f"(c[1]), "+f"(c[2]), "+f"(c[3])
                 : "r"(a[0]), "r"(a[1]), "r"(a[2]), "r"(a[3]), "r"(b0), "r"(b1));
}

// ---------------- 8-warp producer stats (k_conv) ----------------
__device__ __forceinline__ void emit8(const float* v, int slotBase, int blkId) {
    __shared__ float rs[8][64], rq[8][64];
    int lane = threadIdx.x & 31, w = threadIdx.x >> 5;
#pragma unroll
    for (int o = 0; o < CO; o++) {
        float s = v[o], q = s * s;
#pragma unroll
        for (int d = 16; d; d >>= 1) {
            s += __shfl_xor_sync(0xffffffffu, s, d);
            q += __shfl_xor_sync(0xffffffffu, q, d);
        }
        if (lane == 0) { rs[w][o] = s; rq[w][o] = q; }
    }
    __syncthreads();
    int tid = threadIdx.x;
    if (tid < 128) {
        int o = tid & 63;
        float a = 0.f;
        if (tid < 64) {
#pragma unroll
            for (int ww = 0; ww < 8; ww++) a += rs[ww][o];
        } else {
#pragma unroll
            for (int ww = 0; ww < 8; ww++) a += rq[ww][o];
        }
        g_partf[((size_t)(slotBase + o) * NBLK2 + blkId) * 2 + (tid >= 64 ? 1 : 0)] = a;
    }
}

// ---------------- fold1: sig->ps weights, pre-split tf32 ----------------
__global__ void k_fold1(const float* __restrict__ spW, const float* __restrict__ spb,
                        const float* __restrict__ tpW, const float* __restrict__ tpb,
                        const float* __restrict__ psw, const float* __restrict__ psb)
{
    int tid = threadIdx.x;
    for (int idx = tid; idx < CO * KS; idx += blockDim.x) {
        int o = idx / KS, k = idx % KS;
        float w = 0.f;
        if (k < SIGC) {               // temporal features (right half of psw)
            for (int c = 0; c < CO; c++) w = fmaf(tpW[k * CO + c], psw[o * 128 + 64 + c], w);
        } else {                      // spatial features (left half)
            int kk = k - SIGC;
            for (int c = 0; c < CO; c++) w = fmaf(spW[kk * CO + c], psw[o * 128 + c], w);
        }
        uint32_t hi, lo;
        split_tf32(w, hi, lo);
        g_Bsig_hi[idx] = hi;
        g_Bsig_lo[idx] = lo;
    }
    if (tid < CO) {
        float bsum = psb[tid];
        for (int c = 0; c < CO; c++) {
            bsum = fmaf(spb[c], psw[tid * 128 + c],      bsum);
            bsum = fmaf(tpb[c], psw[tid * 128 + 64 + c], bsum);
        }
        g_psb[tid] = bsum;
    }
}

// ---------------- conv stats ONLY (values recomputed in k_fu) ----------------
__global__ __launch_bounds__(256) void k_conv(const float* __restrict__ x,
                                              const float* __restrict__ cw,
                                              const float* __restrict__ cb)
{
    __shared__ float ws[CO * 9];
    __shared__ float bs[CO];
    int j = blockIdx.x, b = blockIdx.y;
    int tid = threadIdx.x, t = tid;
    for (int i = tid; i < CO * 9; i += 256) ws[i] = cw[i];
    if (tid < CO) bs[tid] = cb[tid];
    __syncthreads();

    float xv[9];
#pragma unroll
    for (int c = 0; c < 3; c++) {
        const float* xr = x + (((size_t)b * 3 + c) * JJ + j) * TT;
        xv[c * 3 + 0] = (t > 0)      ? xr[t - 1] : 0.f;
        xv[c * 3 + 1] = xr[t];
        xv[c * 3 + 2] = (t < TT - 1) ? xr[t + 1] : 0.f;
    }
    float val[CO];
#pragma unroll
    for (int o = 0; o < CO; o++) {
        const float* w = ws + o * 9;
        float r = bs[o];
#pragma unroll
        for (int k = 0; k < 9; k++) r = fmaf(xv[k], w[k], r);
        val[o] = fmaxf(r, 0.f);
    }
    emit8(val, 0, b * JJ + j);
}

// ---------------- profiling alignment nop (makes k_sig the 4th launch) ----------------
__global__ void k_nop() {}

// ---------------- signature features ----------------
__device__ __forceinline__ void chen_step(float S1[4], float S2[16], float S3[64], const float d[4])
{
    float B2[16];
#pragma unroll
    for (int i = 0; i < 4; i++)
#pragma unroll
        for (int jx = 0; jx < 4; jx++)
            B2[i * 4 + jx] = 0.5f * d[i] * d[jx];
#pragma unroll
    for (int i = 0; i < 4; i++) {
        float f = fmaf(d[i], (1.f / 3.f), S1[i]);
#pragma unroll
        for (int jx = 0; jx < 4; jx++) {
            float s2 = S2[i * 4 + jx];
#pragma unroll
            for (int k = 0; k < 4; k++)
                S3[i * 16 + jx * 4 + k] += f * B2[jx * 4 + k] + s2 * d[k];
        }
    }
#pragma unroll
    for (int i = 0; i < 4; i++)
#pragma unroll
        for (int jx = 0; jx < 4; jx++)
            S2[i * 4 + jx] += B2[i * 4 + jx] + S1[i] * d[jx];
#pragma unroll
    for (int i = 0; i < 4; i++) S1[i] += d[i];
}

__device__ __forceinline__ void sig_feat(const float p0[3], const float p1[3], const float p2[3],
                                         float* __restrict__ arow)
{
    float a[4], bv[4], cv[4];
    a[0] = 0.f; bv[0] = 0.5f; cv[0] = 0.5f;
#pragma unroll
    for (int c = 0; c < 3; c++) {
        a [c + 1] = p0[c];
        bv[c + 1] = p1[c] - p0[c];
        cv[c + 1] = p2[c] - p1[c];
    }
    float S1[4], S2[16], S3[64];
#pragma unroll
    for (int i = 0; i < 4; i++) S1[i] = a[i];
#pragma unroll
    for (int i = 0; i < 4; i++)
#pragma unroll
        for (int jx = 0; jx < 4; jx++)
            S2[i * 4 + jx] = 0.5f * a[i] * a[jx];
#pragma unroll
    for (int i = 0; i < 4; i++)
#pragma unroll
        for (int jx = 0; jx < 4; jx++)
#pragma unroll
            for (int k = 0; k < 4; k++)
                S3[i * 16 + jx * 4 + k] = S2[i * 4 + jx] * a[k] * (1.f / 3.f);
    chen_step(S1, S2, S3, bv);
    chen_step(S1, S2, S3, cv);
#pragma unroll
    for (int i = 0; i < 4; i++)  arow[i]      = S1[i];
#pragma unroll
    for (int i = 0; i < 16; i++) arow[4 + i]  = S2[i];
#pragma unroll
    for (int i = 0; i < 64; i++) arow[20 + i] = S3[i];
}

// ---------------- k_sig: features + tf32 MMA (M=128,N=64,K=168), B pre-split ----------------
#define SIG_BHI  0
#define SIG_BLO  10816
#define SIG_PSB  21632
#define SIG_A    21696
#define SIG_WORDS (21696 + 128*STS)     /* 43328 words = 173 KB */

__global__ __launch_bounds__(256, 1) void k_sig(const float* __restrict__ x,
                                                const int* __restrict__ nbr)
{
    extern __shared__ float sm[];
    uint32_t* Bhi = (uint32_t*)(sm + SIG_BHI);
    uint32_t* Blo = (uint32_t*)(sm + SIG_BLO);
    float* psb_sh = sm + SIG_PSB;
    float* As     = sm + SIG_A;
    float* Csh    = As;

    int tid = threadIdx.x, wid = tid >> 5, lane = tid & 31;
    int bi = blockIdx.x;
    int h = bi & 1, j = (bi >> 1) % JJ, b = (bi >> 1) / JJ;

    for (int i = tid; i < CO * KS; i += 256) {
        int o = i / KS, k = i % KS;
        Bhi[o * STS + k] = g_Bsig_hi[i];
        Blo[o * STS + k] = g_Bsig_lo[i];
    }
    if (tid < CO) psb_sh[tid] = g_psb[tid];

    int row = tid & 127;
    int t = h * 128 + row;
    if (tid < 128) {
        int tm = (t > 0) ? t - 1 : 0;
        int tp = (t < TT - 1) ? t + 1 : TT - 1;
        float p0[3], p1[3], p2[3];
#pragma unroll
        for (int c = 0; c < 3; c++) {
            const float* xr = x + (((size_t)b * 3 + c) * JJ + j) * TT;
            p0[c] = xr[tm]; p1[c] = xr[t]; p2[c] = xr[tp];
        }
        sig_feat(p0, p1, p2, As + row * STS);
    } else {
        int n0 = nbr[j * 3 + 0], n1 = nbr[j * 3 + 1], n2 = nbr[j * 3 + 2];
        float p0[3], p1[3], p2[3];
#pragma unroll
        for (int c = 0; c < 3; c++) {
            p0[c] = x[(((size_t)b * 3 + c) * JJ + n0) * TT + t];
            p1[c] = x[(((size_t)b * 3 + c) * JJ + n1) * TT + t];
            p2[c] = x[(((size_t)b * 3 + c) * JJ + n2) * TT + t];
        }
        sig_feat(p0, p1, p2, As + row * STS + SIGC);
    }
    __syncthreads();

    float C[8][4];
#pragma unroll
    for (int nt = 0; nt < 8; nt++)
#pragma unroll
        for (int i = 0; i < 4; i++) C[nt][i] = 0.f;

    int qr = lane >> 2, ql = lane & 3;
    const float* aP0 = As + (16 * wid + qr) * STS;
    const float* aP1 = aP0 + 8 * STS;

    for (int ks = 0; ks < KS / 8; ks++) {
        int k0 = ks * 8 + ql;
        uint32_t ah[4], al[4];
        split_tf32(aP0[k0],     ah[0], al[0]);
        split_tf32(aP1[k0],     ah[1], al[1]);
        split_tf32(aP0[k0 + 4], ah[2], al[2]);
        split_tf32(aP1[k0 + 4], ah[3], al[3]);
#pragma unroll
        for (int nt = 0; nt < 8; nt++) {
            int bidx = (nt * 8 + qr) * STS + k0;
            uint32_t bh0 = Bhi[bidx], bh1 = Bhi[bidx + 4];
            uint32_t bl0 = Blo[bidx], bl1 = Blo[bidx + 4];
            mma_tf32(C[nt], ah, bh0, bh1);
            mma_tf32(C[nt], ah, bl0, bl1);
            mma_tf32(C[nt], al, bh0, bh1);
        }
    }
    __syncthreads();

    // epilogue: fragments -> Csh (stride 65) with bias+relu
    int m0 = 16 * wid + qr;
#pragma unroll
    for (int nt = 0; nt < 8; nt++) {
        int n0 = nt * 8 + 2 * ql;
        Csh[m0 * 65 + n0]           = fmaxf(C[nt][0] + psb_sh[n0],     0.f);
        Csh[m0 * 65 + n0 + 1]       = fmaxf(C[nt][1] + psb_sh[n0 + 1], 0.f);
        Csh[(m0 + 8) * 65 + n0]     = fmaxf(C[nt][2] + psb_sh[n0],     0.f);
        Csh[(m0 + 8) * 65 + n0 + 1] = fmaxf(C[nt][3] + psb_sh[n0 + 1], 0.f);
    }
    __syncthreads();

    // coalesced write + stats: o per 4 lanes, conflict-free column reads
    int o = tid >> 2, g = tid & 3;
    float* gp = g_sig + ((size_t)b * CO + o) * ROW + j * TT + h * 128;
    float s = 0.f, q = 0.f;
#pragma unroll
    for (int it = 0; it < 8; it++) {
        int tt = it * 16 + g * 4;
        float v0 = Csh[(tt + 0) * 65 + o];
        float v1 = Csh[(tt + 1) * 65 + o];
        float v2 = Csh[(tt + 2) * 65 + o];
        float v3 = Csh[(tt + 3) * 65 + o];
        s += v0 + v1 + v2 + v3;
        q += v0 * v0 + v1 * v1 + v2 * v2 + v3 * v3;
        *(float4*)(gp + tt) = make_float4(v0, v1, v2, v3);
    }
    s += __shfl_xor_sync(0xffffffffu, s, 1);
    q += __shfl_xor_sync(0xffffffffu, q, 1);
    s += __shfl_xor_sync(0xffffffffu, s, 2);
    q += __shfl_xor_sync(0xffffffffu, q, 2);
    if (g == 0) {
        g_partf[((size_t)(64 + o) * NBLK2 + bi) * 2 + 0] = s;
        g_partf[((size_t)(64 + o) * NBLK2 + bi) * 2 + 1] = q;
    }
}

// ---------------- combine partials -> per-slot {sum, sumsq} (double) ----------------
__global__ void k_reduce(int slotBase)
{
    int slot = slotBase + blockIdx.x;
    int nblk = (slot >= 64 && slot < 128) ? 3200 : 1600;
    int tid = threadIdx.x;
    const float2* p = reinterpret_cast<const float2*>(g_partf + (size_t)slot * NBLK2 * 2);
    double s = 0.0, q = 0.0;
    for (int i = tid; i < nblk; i += 256) {
        float2 v = p[i];
        s += (double)v.x;
        q += (double)v.y;
    }
    __shared__ double ss[256], sq[256];
    ss[tid] = s; sq[tid] = q;
    __syncthreads();
    for (int st = 128; st > 0; st >>= 1) {
        if (tid < st) { ss[tid] += ss[tid + st]; sq[tid] += sq[tid + st]; }
        __syncthreads();
    }
    if (tid == 0) {
        g_stat[slot * 2 + 0] = ss[0];
        g_stat[slot * 2 + 1] = sq[0];
    }
}

// ---------------- fold2: BN affines -> fu weights, pre-split tf32 ----------------
__global__ void k_fold2(const float* __restrict__ rg, const float* __restrict__ rb,
                        const float* __restrict__ pg, const float* __restrict__ pb,
                        const float* __restrict__ fuw, const float* __restrict__ fub)
{
    __shared__ float scale_sh[128], shift_sh[128];
    int tid = threadIdx.x;
    if (tid < 128) {
        double s = g_stat[tid * 2 + 0];
        double q = g_stat[tid * 2 + 1];
        double mean = s / (double)NPIX;
        double var  = q / (double)NPIX - mean * mean;
        float gamma = (tid < 64) ? rg[tid] : pg[tid - 64];
        float beta  = (tid < 64) ? rb[tid] : pb[tid - 64];
        double sc = (double)gamma / sqrt(var + EPSV);
        scale_sh[tid] = (float)sc;
        shift_sh[tid] = (float)((double)beta - mean * sc);
    }
    __syncthreads();
    for (int idx = tid; idx < CO * KF; idx += blockDim.x) {
        int o = idx / KF, c = idx % KF;
        float w = fuw[o * 128 + c] * scale_sh[c];
        uint32_t hi, lo;
        split_tf32(w, hi, lo);
        g_Bfu_hi[idx] = hi;
        g_Bfu_lo[idx] = lo;
    }
    if (tid < CO) {
        double bsum = fub[tid];
        for (int c = 0; c < 128; c++)
            bsum += (double)fuw[tid * 128 + c] * (double)shift_sh[c];
        g_fub[tid] = (float)bsum;
    }
}

// ---------------- k_fu: conv recompute + fusion GEMM (M=256,N=64,K=128) ----------------
#define FU_BHI  0
#define FU_BLO  8768
#define FU_FB   17536
#define FU_WS   17600
#define FU_CB   18176
#define FU_A    18240
#define FU_WORDS (18240 + 256*STF)      /* 53312 words = 213 KB */

__global__ __launch_bounds__(512, 1) void k_fu(const float* __restrict__ x,
                                               const float* __restrict__ cw,
                                               const float* __restrict__ cb)
{
    extern __shared__ float sm[];
    uint32_t* Bhi = (uint32_t*)(sm + FU_BHI);
    uint32_t* Blo = (uint32_t*)(sm + FU_BLO);
    float* fb_sh = sm + FU_FB;
    float* ws    = sm + FU_WS;
    float* cbs   = sm + FU_CB;
    float* Af    = sm + FU_A;
    float* Csh   = Af;

    int tid = threadIdx.x, wid = tid >> 5, lane = tid & 31;
    int bi = blockIdx.x;
    int j = bi % JJ, b = bi / JJ;

    for (int i = tid; i < CO * KF; i += 512) {
        int o = i / KF, k = i % KF;
        Bhi[o * STF + k] = g_Bfu_hi[i];
        Blo[o * STF + k] = g_Bfu_lo[i];
    }
    for (int i = tid; i < CO * 9; i += 512) ws[i] = cw[i];
    if (tid < CO) { cbs[tid] = cb[tid]; fb_sh[tid] = g_fub[tid]; }
    __syncthreads();

    if (tid < 256) {
        // recompute conv (bitwise identical to k_conv) for rows t = tid
        int t = tid;
        float xv[9];
#pragma unroll
        for (int c = 0; c < 3; c++) {
            const float* xr = x + (((size_t)b * 3 + c) * JJ + j) * TT;
            xv[c * 3 + 0] = (t > 0)      ? xr[t - 1] : 0.f;
            xv[c * 3 + 1] = xr[t];
            xv[c * 3 + 2] = (t < TT - 1) ? xr[t + 1] : 0.f;
        }
        float* arow = Af + t * STF;
#pragma unroll 4
        for (int o = 0; o < CO; o++) {
            const float* w = ws + o * 9;
            float r = cbs[o];
#pragma unroll
            for (int k = 0; k < 9; k++) r = fmaf(xv[k], w[k], r);
            arow[o] = fmaxf(r, 0.f);
        }
    } else {
        int t = tid - 256;
        float* arow = Af + t * STF + 64;
        size_t sb2 = ((size_t)b * CO) * ROW + j * TT + t;
#pragma unroll 8
        for (int c = 0; c < CO; c++)
            arow[c] = g_sig[sb2 + (size_t)c * ROW];
    }
    __syncthreads();

    float C[8][4];
#pragma unroll
    for (int nt = 0; nt < 8; nt++)
#pragma unroll
        for (int i = 0; i < 4; i++) C[nt][i] = 0.f;

    int qr = lane >> 2, ql = lane & 3;
    const float* aP0 = Af + (16 * wid + qr) * STF;
    const float* aP1 = aP0 + 8 * STF;

    for (int ks = 0; ks < KF / 8; ks++) {
        int k0 = ks * 8 + ql;
        uint32_t ah[4], al[4];
        split_tf32(aP0[k0],     ah[0], al[0]);
        split_tf32(aP1[k0],     ah[1], al[1]);
        split_tf32(aP0[k0 + 4], ah[2], al[2]);
        split_tf32(aP1[k0 + 4], ah[3], al[3]);
#pragma unroll
        for (int nt = 0; nt < 8; nt++) {
            int bidx = (nt * 8 + qr) * STF + k0;
            uint32_t bh0 = Bhi[bidx], bh1 = Bhi[bidx + 4];
            uint32_t bl0 = Blo[bidx], bl1 = Blo[bidx + 4];
            mma_tf32(C[nt], ah, bh0, bh1);
            mma_tf32(C[nt], ah, bl0, bl1);
            mma_tf32(C[nt], al, bh0, bh1);
        }
    }
    __syncthreads();

    int m0 = 16 * wid + qr;
#pragma unroll
    for (int nt = 0; nt < 8; nt++) {
        int n0 = nt * 8 + 2 * ql;
        Csh[m0 * 65 + n0]           = fmaxf(C[nt][0] + fb_sh[n0],     0.f);
        Csh[m0 * 65 + n0 + 1]       = fmaxf(C[nt][1] + fb_sh[n0 + 1], 0.f);
        Csh[(m0 + 8) * 65 + n0]     = fmaxf(C[nt][2] + fb_sh[n0],     0.f);
        Csh[(m0 + 8) * 65 + n0 + 1] = fmaxf(C[nt][3] + fb_sh[n0 + 1], 0.f);
    }
    __syncthreads();

    int o = tid >> 3, g = tid & 7;
    float* gp = g_y + ((size_t)b * CO + o) * ROW + j * TT;
    float s = 0.f, q = 0.f;
#pragma unroll
    for (int it = 0; it < 8; it++) {
        int tt = it * 32 + g * 4;
        float v0 = Csh[(tt + 0) * 65 + o];
        float v1 = Csh[(tt + 1) * 65 + o];
        float v2 = Csh[(tt + 2) * 65 + o];
        float v3 = Csh[(tt + 3) * 65 + o];
        s += v0 + v1 + v2 + v3;
        q += v0 * v0 + v1 * v1 + v2 * v2 + v3 * v3;
        *(float4*)(gp + tt) = make_float4(v0, v1, v2, v3);
    }
    s += __shfl_xor_sync(0xffffffffu, s, 1);
    q += __shfl_xor_sync(0xffffffffu, q, 1);
    s += __shfl_xor_sync(0xffffffffu, s, 2);
    q += __shfl_xor_sync(0xffffffffu, q, 2);
    s += __shfl_xor_sync(0xffffffffu, s, 4);
    q += __shfl_xor_sync(0xffffffffu, q, 4);
    if (g == 0) {
        g_partf[((size_t)(128 + o) * NBLK2 + bi) * 2 + 0] = s;
        g_partf[((size_t)(128 + o) * NBLK2 + bi) * 2 + 1] = q;
    }
}

// ---------------- finalize BN(y) ----------------
__global__ void k_bny(const float* __restrict__ fg, const float* __restrict__ fbt)
{
    int tid = threadIdx.x;
    if (tid < CO) {
        double s = g_stat[(128 + tid) * 2 + 0];
        double q = g_stat[(128 + tid) * 2 + 1];
        double mean = s / (double)NPIX;
        double var  = q / (double)NPIX - mean * mean;
        double sc = (double)fg[tid] / sqrt(var + EPSV);
        g_bny_scale[tid] = (float)sc;
        g_bny_shift[tid] = (float)((double)fbt[tid] - mean * sc);
    }
}

// ---------------- apply final BN, write output ----------------
__global__ void k_apply(float* __restrict__ out)
{
    int i = blockIdx.x * 256 + threadIdx.x;   // float4 index
    float4 v = reinterpret_cast<const float4*>(g_y)[i];
    int c = (i / (ROW / 4)) & 63;
    float sc = g_bny_scale[c], sf = g_bny_shift[c];
    float4 r;
    r.x = fmaf(v.x, sc, sf);
    r.y = fmaf(v.y, sc, sf);
    r.z = fmaf(v.z, sc, sf);
    r.w = fmaf(v.w, sc, sf);
    reinterpret_cast<float4*>(out)[i] = r;
}

// ---------------- launch ----------------
extern "C" void kernel_launch(void* const* d_in, const int* in_sizes, int n_in,
                              void* d_out, int out_size)
{
    const float* x      = (const float*)d_in[0];
    const float* conv_w = (const float*)d_in[1];
    const float* conv_b = (const float*)d_in[2];
    const float* raw_g  = (const float*)d_in[3];
    const float* raw_b  = (const float*)d_in[4];
    const float* sp_W   = (const float*)d_in[5];
    const float* sp_b   = (const float*)d_in[6];
    const float* tp_W   = (const float*)d_in[7];
    const float* tp_b   = (const float*)d_in[8];
    const float* ps_w   = (const float*)d_in[9];
    const float* ps_b   = (const float*)d_in[10];
    const float* ps_g   = (const float*)d_in[11];
    const float* ps_bt  = (const float*)d_in[12];
    const float* fu_w   = (const float*)d_in[13];
    const float* fu_b   = (const float*)d_in[14];
    const float* fu_g   = (const float*)d_in[15];
    const float* fu_bt  = (const float*)d_in[16];
    const int*   nbr    = (const int*)d_in[17];
    float* out          = (float*)d_out;

    cudaFuncSetAttribute(k_sig, cudaFuncAttributeMaxDynamicSharedMemorySize, SIG_WORDS * 4);
    cudaFuncSetAttribute(k_fu,  cudaFuncAttributeMaxDynamicSharedMemorySize, FU_WORDS * 4);

    k_fold1 <<<1, 256>>>(sp_W, sp_b, tp_W, tp_b, ps_w, ps_b);
    k_conv  <<<dim3(JJ, BB), 256>>>(x, conv_w, conv_b);
    k_nop   <<<1, 32>>>();
    k_sig   <<<BB * JJ * 2, 256, SIG_WORDS * 4>>>(x, nbr);
    k_reduce<<<128, 256>>>(0);
    k_fold2 <<<1, 256>>>(raw_g, raw_b, ps_g, ps_bt, fu_w, fu_b);
    k_fu    <<<BB * JJ, 512, FU_WORDS * 4>>>(x, conv_w, conv_b);
    k_reduce<<<64, 256>>>(128);
    k_bny   <<<1, 64>>>(fu_g, fu_bt);
    k_apply <<<(BB * CO * ROW) / 1024, 256>>>(out);
}

// round 10
// speedup vs baseline: 2.1445x; 1.1895x over previous
#include <cuda_runtime.h>
#include <math.h>
#include <stdint.h>

// Problem dims
#define BB   64
#define JJ   25
#define TT   256
#define CO   64
#define ROW  (JJ*TT)            /* 6400 */
#define SIGC 84
#define NPIX (BB*JJ*TT)         /* 409600 per channel */
#define NBLK 1600               /* producer blocks per stats slot */
#define EPSV 1e-5

#define KS   168                /* sig GEMM K */
#define KF   128                /* fusion GEMM K */
#define STS  169                /* word stride, 169 % 32 == 9 (conflict-free-ish) */
#define STF  137                /* word stride, 137 % 32 == 9 */

// ---------------- scratch (static device allocations: allowed) ----------------
__device__ float    g_sig[(size_t)BB*CO*ROW];
__device__ float    g_y  [(size_t)BB*CO*ROW];
__device__ float    g_psb[CO];
__device__ float    g_fub[CO];
__device__ uint32_t g_Bsig_hi[CO*KS];   // tf32 bit patterns, [o][k]
__device__ uint32_t g_Bfu_hi[CO*KF];    // BN folded
__device__ float    g_partf[(size_t)192*NBLK*2];
__device__ double   g_stat[192*2];
__device__ float    g_bny_scale[CO];
__device__ float    g_bny_shift[CO];

// ---------------- tf32 mma helpers ----------------
__device__ __forceinline__ void split_tf32(float f, uint32_t& hi, uint32_t& lo) {
    asm("cvt.rna.tf32.f32 %0, %1;" : "=r"(hi) : "f"(f));
    float r = f - __uint_as_float(hi);
    asm("cvt.rna.tf32.f32 %0, %1;" : "=r"(lo) : "f"(r));
}
__device__ __forceinline__ uint32_t to_tf32(float f) {
    uint32_t u;
    asm("cvt.rna.tf32.f32 %0, %1;" : "=r"(u) : "f"(f));
    return u;
}
__device__ __forceinline__ void mma_tf32(float* c, const uint32_t* a, uint32_t b0, uint32_t b1) {
    asm volatile("mma.sync.aligned.m16n8k8.row.col.f32.tf32.tf32.f32 "
                 "{%0,%1,%2,%3}, {%4,%5,%6,%7}, {%8,%9}, {%0,%1,%2,%3};"
                 : "+f"(c[0]), "+f"(c[1]), "+f"(c[2]), "+f"(c[3])
                 : "r"(a[0]), "r"(a[1]), "r"(a[2]), "r"(a[3]), "r"(b0), "r"(b1));
}

// ---------------- 8-warp producer stats (k_conv) ----------------
__device__ __forceinline__ void emit8(const float* v, int slotBase, int blkId) {
    __shared__ float rs[8][64], rq[8][64];
    int lane = threadIdx.x & 31, w = threadIdx.x >> 5;
#pragma unroll
    for (int o = 0; o < CO; o++) {
        float s = v[o], q = s * s;
#pragma unroll
        for (int d = 16; d; d >>= 1) {
            s += __shfl_xor_sync(0xffffffffu, s, d);
            q += __shfl_xor_sync(0xffffffffu, q, d);
        }
        if (lane == 0) { rs[w][o] = s; rq[w][o] = q; }
    }
    __syncthreads();
    int tid = threadIdx.x;
    if (tid < 128) {
        int o = tid & 63;
        float a = 0.f;
        if (tid < 64) {
#pragma unroll
            for (int ww = 0; ww < 8; ww++) a += rs[ww][o];
        } else {
#pragma unroll
            for (int ww = 0; ww < 8; ww++) a += rq[ww][o];
        }
        g_partf[((size_t)(slotBase + o) * NBLK + blkId) * 2 + (tid >= 64 ? 1 : 0)] = a;
    }
}

// ---------------- fold1: sig->ps weights -> tf32 image ----------------
__global__ void k_fold1(const float* __restrict__ spW, const float* __restrict__ spb,
                        const float* __restrict__ tpW, const float* __restrict__ tpb,
                        const float* __restrict__ psw, const float* __restrict__ psb)
{
    int tid = threadIdx.x;
    for (int idx = tid; idx < CO * KS; idx += blockDim.x) {
        int o = idx / KS, k = idx % KS;
        float w = 0.f;
        if (k < SIGC) {               // temporal features (right half of psw)
            for (int c = 0; c < CO; c++) w = fmaf(tpW[k * CO + c], psw[o * 128 + 64 + c], w);
        } else {                      // spatial features (left half)
            int kk = k - SIGC;
            for (int c = 0; c < CO; c++) w = fmaf(spW[kk * CO + c], psw[o * 128 + c], w);
        }
        g_Bsig_hi[idx] = to_tf32(w);
    }
    if (tid < CO) {
        float bsum = psb[tid];
        for (int c = 0; c < CO; c++) {
            bsum = fmaf(spb[c], psw[tid * 128 + c],      bsum);
            bsum = fmaf(tpb[c], psw[tid * 128 + 64 + c], bsum);
        }
        g_psb[tid] = bsum;
    }
}

// ---------------- conv stats ONLY (values recomputed in k_fu) ----------------
__global__ __launch_bounds__(256) void k_conv(const float* __restrict__ x,
                                              const float* __restrict__ cw,
                                              const float* __restrict__ cb)
{
    __shared__ float ws[CO * 9];
    __shared__ float bs[CO];
    int j = blockIdx.x, b = blockIdx.y;
    int tid = threadIdx.x, t = tid;
    for (int i = tid; i < CO * 9; i += 256) ws[i] = cw[i];
    if (tid < CO) bs[tid] = cb[tid];
    __syncthreads();

    float xv[9];
#pragma unroll
    for (int c = 0; c < 3; c++) {
        const float* xr = x + (((size_t)b * 3 + c) * JJ + j) * TT;
        xv[c * 3 + 0] = (t > 0)      ? xr[t - 1] : 0.f;
        xv[c * 3 + 1] = xr[t];
        xv[c * 3 + 2] = (t < TT - 1) ? xr[t + 1] : 0.f;
    }
    float val[CO];
#pragma unroll
    for (int o = 0; o < CO; o++) {
        const float* w = ws + o * 9;
        float r = bs[o];
#pragma unroll
        for (int k = 0; k < 9; k++) r = fmaf(xv[k], w[k], r);
        val[o] = fmaxf(r, 0.f);
    }
    emit8(val, 0, b * JJ + j);
}

// ---------------- profiling alignment nop (keeps k_sig the 4th launch) ----------------
__global__ void k_nop() {}

// ---------------- signature features ----------------
__device__ __forceinline__ void chen_step(float S1[4], float S2[16], float S3[64], const float d[4])
{
    float B2[16];
#pragma unroll
    for (int i = 0; i < 4; i++)
#pragma unroll
        for (int jx = 0; jx < 4; jx++)
            B2[i * 4 + jx] = 0.5f * d[i] * d[jx];
#pragma unroll
    for (int i = 0; i < 4; i++) {
        float f = fmaf(d[i], (1.f / 3.f), S1[i]);
#pragma unroll
        for (int jx = 0; jx < 4; jx++) {
            float s2 = S2[i * 4 + jx];
#pragma unroll
            for (int k = 0; k < 4; k++)
                S3[i * 16 + jx * 4 + k] += f * B2[jx * 4 + k] + s2 * d[k];
        }
    }
#pragma unroll
    for (int i = 0; i < 4; i++)
#pragma unroll
        for (int jx = 0; jx < 4; jx++)
            S2[i * 4 + jx] += B2[i * 4 + jx] + S1[i] * d[jx];
#pragma unroll
    for (int i = 0; i < 4; i++) S1[i] += d[i];
}

__device__ __forceinline__ void sig_feat(const float p0[3], const float p1[3], const float p2[3],
                                         float* __restrict__ arow)
{
    float a[4], bv[4], cv[4];
    a[0] = 0.f; bv[0] = 0.5f; cv[0] = 0.5f;
#pragma unroll
    for (int c = 0; c < 3; c++) {
        a [c + 1] = p0[c];
        bv[c + 1] = p1[c] - p0[c];
        cv[c + 1] = p2[c] - p1[c];
    }
    float S1[4], S2[16], S3[64];
#pragma unroll
    for (int i = 0; i < 4; i++) S1[i] = a[i];
#pragma unroll
    for (int i = 0; i < 4; i++)
#pragma unroll
        for (int jx = 0; jx < 4; jx++)
            S2[i * 4 + jx] = 0.5f * a[i] * a[jx];
#pragma unroll
    for (int i = 0; i < 4; i++)
#pragma unroll
        for (int jx = 0; jx < 4; jx++)
#pragma unroll
            for (int k = 0; k < 4; k++)
                S3[i * 16 + jx * 4 + k] = S2[i * 4 + jx] * a[k] * (1.f / 3.f);
    chen_step(S1, S2, S3, bv);
    chen_step(S1, S2, S3, cv);
#pragma unroll
    for (int i = 0; i < 4; i++)  arow[i]      = S1[i];
#pragma unroll
    for (int i = 0; i < 16; i++) arow[4 + i]  = S2[i];
#pragma unroll
    for (int i = 0; i < 64; i++) arow[20 + i] = S3[i];
}

// ---------------- k_sig: features + tf32 MMA (M=256,N=64,K=168) ----------------
#define SIG_BHI  0
#define SIG_PSB  10816
#define SIG_A    10880
#define SIG_WORDS (10880 + 256*STS)     /* 54144 words = 216,576 B */

__global__ __launch_bounds__(512, 1) void k_sig(const float* __restrict__ x,
                                                const int* __restrict__ nbr)
{
    extern __shared__ float sm[];
    uint32_t* Bhi = (uint32_t*)(sm + SIG_BHI);
    float* psb_sh = sm + SIG_PSB;
    float* As     = sm + SIG_A;
    float* Csh    = As;

    int tid = threadIdx.x, wid = tid >> 5, lane = tid & 31;
    int bi = blockIdx.x;
    int j = bi % JJ, b = bi / JJ;

    for (int i = tid; i < CO * KS; i += 512) {
        int o = i / KS, k = i % KS;
        Bhi[o * STS + k] = g_Bsig_hi[i];
    }
    if (tid < CO) psb_sh[tid] = g_psb[tid];

    if (tid < 256) {
        int t = tid;
        int tm = (t > 0) ? t - 1 : 0;
        int tp = (t < TT - 1) ? t + 1 : TT - 1;
        float p0[3], p1[3], p2[3];
#pragma unroll
        for (int c = 0; c < 3; c++) {
            const float* xr = x + (((size_t)b * 3 + c) * JJ + j) * TT;
            p0[c] = xr[tm]; p1[c] = xr[t]; p2[c] = xr[tp];
        }
        sig_feat(p0, p1, p2, As + t * STS);
    } else {
        int t = tid - 256;
        int n0 = nbr[j * 3 + 0], n1 = nbr[j * 3 + 1], n2 = nbr[j * 3 + 2];
        float p0[3], p1[3], p2[3];
#pragma unroll
        for (int c = 0; c < 3; c++) {
            p0[c] = x[(((size_t)b * 3 + c) * JJ + n0) * TT + t];
            p1[c] = x[(((size_t)b * 3 + c) * JJ + n1) * TT + t];
            p2[c] = x[(((size_t)b * 3 + c) * JJ + n2) * TT + t];
        }
        sig_feat(p0, p1, p2, As + t * STS + SIGC);
    }
    __syncthreads();

    float C[8][4];
#pragma unroll
    for (int nt = 0; nt < 8; nt++)
#pragma unroll
        for (int i = 0; i < 4; i++) C[nt][i] = 0.f;

    int qr = lane >> 2, ql = lane & 3;
    const float* aP0 = As + (16 * wid + qr) * STS;
    const float* aP1 = aP0 + 8 * STS;

    for (int ks = 0; ks < KS / 8; ks++) {
        int k0 = ks * 8 + ql;
        uint32_t ah[4], al[4];
        split_tf32(aP0[k0],     ah[0], al[0]);
        split_tf32(aP1[k0],     ah[1], al[1]);
        split_tf32(aP0[k0 + 4], ah[2], al[2]);
        split_tf32(aP1[k0 + 4], ah[3], al[3]);
#pragma unroll
        for (int nt = 0; nt < 8; nt++) {
            int bidx = (nt * 8 + qr) * STS + k0;
            uint32_t bh0 = Bhi[bidx], bh1 = Bhi[bidx + 4];
            mma_tf32(C[nt], ah, bh0, bh1);
            mma_tf32(C[nt], al, bh0, bh1);
        }
    }
    __syncthreads();

    // epilogue: fragments -> Csh (stride 65) with bias+relu
    int m0 = 16 * wid + qr;
#pragma unroll
    for (int nt = 0; nt < 8; nt++) {
        int n0 = nt * 8 + 2 * ql;
        Csh[m0 * 65 + n0]           = fmaxf(C[nt][0] + psb_sh[n0],     0.f);
        Csh[m0 * 65 + n0 + 1]       = fmaxf(C[nt][1] + psb_sh[n0 + 1], 0.f);
        Csh[(m0 + 8) * 65 + n0]     = fmaxf(C[nt][2] + psb_sh[n0],     0.f);
        Csh[(m0 + 8) * 65 + n0 + 1] = fmaxf(C[nt][3] + psb_sh[n0 + 1], 0.f);
    }
    __syncthreads();

    // coalesced write + stats
    int o = tid >> 3, g = tid & 7;
    float* gp = g_sig + ((size_t)b * CO + o) * ROW + j * TT;
    float s = 0.f, q = 0.f;
#pragma unroll
    for (int it = 0; it < 8; it++) {
        int tt = it * 32 + g * 4;
        float v0 = Csh[(tt + 0) * 65 + o];
        float v1 = Csh[(tt + 1) * 65 + o];
        float v2 = Csh[(tt + 2) * 65 + o];
        float v3 = Csh[(tt + 3) * 65 + o];
        s += v0 + v1 + v2 + v3;
        q += v0 * v0 + v1 * v1 + v2 * v2 + v3 * v3;
        *(float4*)(gp + tt) = make_float4(v0, v1, v2, v3);
    }
    s += __shfl_xor_sync(0xffffffffu, s, 1);
    q += __shfl_xor_sync(0xffffffffu, q, 1);
    s += __shfl_xor_sync(0xffffffffu, s, 2);
    q += __shfl_xor_sync(0xffffffffu, q, 2);
    s += __shfl_xor_sync(0xffffffffu, s, 4);
    q += __shfl_xor_sync(0xffffffffu, q, 4);
    if (g == 0) {
        g_partf[((size_t)(64 + o) * NBLK + bi) * 2 + 0] = s;
        g_partf[((size_t)(64 + o) * NBLK + bi) * 2 + 1] = q;
    }
}

// ---------------- combine partials -> per-slot {sum, sumsq} (double) ----------------
__global__ void k_reduce(int slotBase)
{
    int slot = slotBase + blockIdx.x;
    int tid = threadIdx.x;
    const float2* p = reinterpret_cast<const float2*>(g_partf + (size_t)slot * NBLK * 2);
    double s = 0.0, q = 0.0;
    for (int i = tid; i < NBLK; i += 256) {
        float2 v = p[i];
        s += (double)v.x;
        q += (double)v.y;
    }
    __shared__ double ss[256], sq[256];
    ss[tid] = s; sq[tid] = q;
    __syncthreads();
    for (int st = 128; st > 0; st >>= 1) {
        if (tid < st) { ss[tid] += ss[tid + st]; sq[tid] += sq[tid + st]; }
        __syncthreads();
    }
    if (tid == 0) {
        g_stat[slot * 2 + 0] = ss[0];
        g_stat[slot * 2 + 1] = sq[0];
    }
}

// ---------------- fold2: BN affines -> fu weights tf32 image ----------------
__global__ void k_fold2(const float* __restrict__ rg, const float* __restrict__ rb,
                        const float* __restrict__ pg, const float* __restrict__ pb,
                        const float* __restrict__ fuw, const float* __restrict__ fub)
{
    __shared__ float scale_sh[128], shift_sh[128];
    int tid = threadIdx.x;
    if (tid < 128) {
        double s = g_stat[tid * 2 + 0];
        double q = g_stat[tid * 2 + 1];
        double mean = s / (double)NPIX;
        double var  = q / (double)NPIX - mean * mean;
        float gamma = (tid < 64) ? rg[tid] : pg[tid - 64];
        float beta  = (tid < 64) ? rb[tid] : pb[tid - 64];
        double sc = (double)gamma / sqrt(var + EPSV);
        scale_sh[tid] = (float)sc;
        shift_sh[tid] = (float)((double)beta - mean * sc);
    }
    __syncthreads();
    for (int idx = tid; idx < CO * KF; idx += blockDim.x) {
        int o = idx / KF, c = idx % KF;
        g_Bfu_hi[idx] = to_tf32(fuw[o * 128 + c] * scale_sh[c]);
    }
    if (tid < CO) {
        double bsum = fub[tid];
        for (int c = 0; c < 128; c++)
            bsum += (double)fuw[tid * 128 + c] * (double)shift_sh[c];
        g_fub[tid] = (float)bsum;
    }
}

// ---------------- k_fu: conv recompute + fusion GEMM (M=256,N=64,K=128) ----------------
#define FU_BHI  0
#define FU_FB   8768
#define FU_WS   8832
#define FU_CB   9408
#define FU_A    9472
#define FU_WORDS (9472 + 256*STF)       /* 44544 words = 178,176 B */

__global__ __launch_bounds__(512, 1) void k_fu(const float* __restrict__ x,
                                               const float* __restrict__ cw,
                                               const float* __restrict__ cb)
{
    extern __shared__ float sm[];
    uint32_t* Bhi = (uint32_t*)(sm + FU_BHI);
    float* fb_sh = sm + FU_FB;
    float* ws    = sm + FU_WS;
    float* cbs   = sm + FU_CB;
    float* Af    = sm + FU_A;
    float* Csh   = Af;

    int tid = threadIdx.x, wid = tid >> 5, lane = tid & 31;
    int bi = blockIdx.x;
    int j = bi % JJ, b = bi / JJ;

    for (int i = tid; i < CO * KF; i += 512) {
        int o = i / KF, k = i % KF;
        Bhi[o * STF + k] = g_Bfu_hi[i];
    }
    for (int i = tid; i < CO * 9; i += 512) ws[i] = cw[i];
    if (tid < CO) { cbs[tid] = cb[tid]; fb_sh[tid] = g_fub[tid]; }
    __syncthreads();

    if (tid < 256) {
        // recompute conv (bitwise identical to k_conv) for rows t = tid
        int t = tid;
        float xv[9];
#pragma unroll
        for (int c = 0; c < 3; c++) {
            const float* xr = x + (((size_t)b * 3 + c) * JJ + j) * TT;
            xv[c * 3 + 0] = (t > 0)      ? xr[t - 1] : 0.f;
            xv[c * 3 + 1] = xr[t];
            xv[c * 3 + 2] = (t < TT - 1) ? xr[t + 1] : 0.f;
        }
        float* arow = Af + t * STF;
#pragma unroll 4
        for (int o = 0; o < CO; o++) {
            const float* w = ws + o * 9;
            float r = cbs[o];
#pragma unroll
            for (int k = 0; k < 9; k++) r = fmaf(xv[k], w[k], r);
            arow[o] = fmaxf(r, 0.f);
        }
    } else {
        int t = tid - 256;
        float* arow = Af + t * STF + 64;
        size_t sb2 = ((size_t)b * CO) * ROW + j * TT + t;
#pragma unroll 8
        for (int c = 0; c < CO; c++)
            arow[c] = g_sig[sb2 + (size_t)c * ROW];
    }
    __syncthreads();

    float C[8][4];
#pragma unroll
    for (int nt = 0; nt < 8; nt++)
#pragma unroll
        for (int i = 0; i < 4; i++) C[nt][i] = 0.f;

    int qr = lane >> 2, ql = lane & 3;
    const float* aP0 = Af + (16 * wid + qr) * STF;
    const float* aP1 = aP0 + 8 * STF;

    for (int ks = 0; ks < KF / 8; ks++) {
        int k0 = ks * 8 + ql;
        uint32_t ah[4], al[4];
        split_tf32(aP0[k0],     ah[0], al[0]);
        split_tf32(aP1[k0],     ah[1], al[1]);
        split_tf32(aP0[k0 + 4], ah[2], al[2]);
        split_tf32(aP1[k0 + 4], ah[3], al[3]);
#pragma unroll
        for (int nt = 0; nt < 8; nt++) {
            int bidx = (nt * 8 + qr) * STF + k0;
            uint32_t bh0 = Bhi[bidx], bh1 = Bhi[bidx + 4];
            mma_tf32(C[nt], ah, bh0, bh1);
            mma_tf32(C[nt], al, bh0, bh1);
        }
    }
    __syncthreads();

    int m0 = 16 * wid + qr;
#pragma unroll
    for (int nt = 0; nt < 8; nt++) {
        int n0 = nt * 8 + 2 * ql;
        Csh[m0 * 65 + n0]           = fmaxf(C[nt][0] + fb_sh[n0],     0.f);
        Csh[m0 * 65 + n0 + 1]       = fmaxf(C[nt][1] + fb_sh[n0 + 1], 0.f);
        Csh[(m0 + 8) * 65 + n0]     = fmaxf(C[nt][2] + fb_sh[n0],     0.f);
        Csh[(m0 + 8) * 65 + n0 + 1] = fmaxf(C[nt][3] + fb_sh[n0 + 1], 0.f);
    }
    __syncthreads();

    int o = tid >> 3, g = tid & 7;
    float* gp = g_y + ((size_t)b * CO + o) * ROW + j * TT;
    float s = 0.f, q = 0.f;
#pragma unroll
    for (int it = 0; it < 8; it++) {
        int tt = it * 32 + g * 4;
        float v0 = Csh[(tt + 0) * 65 + o];
        float v1 = Csh[(tt + 1) * 65 + o];
        float v2 = Csh[(tt + 2) * 65 + o];
        float v3 = Csh[(tt + 3) * 65 + o];
        s += v0 + v1 + v2 + v3;
        q += v0 * v0 + v1 * v1 + v2 * v2 + v3 * v3;
        *(float4*)(gp + tt) = make_float4(v0, v1, v2, v3);
    }
    s += __shfl_xor_sync(0xffffffffu, s, 1);
    q += __shfl_xor_sync(0xffffffffu, q, 1);
    s += __shfl_xor_sync(0xffffffffu, s, 2);
    q += __shfl_xor_sync(0xffffffffu, q, 2);
    s += __shfl_xor_sync(0xffffffffu, s, 4);
    q += __shfl_xor_sync(0xffffffffu, q, 4);
    if (g == 0) {
        g_partf[((size_t)(128 + o) * NBLK + bi) * 2 + 0] = s;
        g_partf[((size_t)(128 + o) * NBLK + bi) * 2 + 1] = q;
    }
}

// ---------------- finalize BN(y) ----------------
__global__ void k_bny(const float* __restrict__ fg, const float* __restrict__ fbt)
{
    int tid = threadIdx.x;
    if (tid < CO) {
        double s = g_stat[(128 + tid) * 2 + 0];
        double q = g_stat[(128 + tid) * 2 + 1];
        double mean = s / (double)NPIX;
        double var  = q / (double)NPIX - mean * mean;
        double sc = (double)fg[tid] / sqrt(var + EPSV);
        g_bny_scale[tid] = (float)sc;
        g_bny_shift[tid] = (float)((double)fbt[tid] - mean * sc);
    }
}

// ---------------- apply final BN, write output ----------------
__global__ void k_apply(float* __restrict__ out)
{
    int i = blockIdx.x * 256 + threadIdx.x;   // float4 index
    float4 v = reinterpret_cast<const float4*>(g_y)[i];
    int c = (i / (ROW / 4)) & 63;
    float sc = g_bny_scale[c], sf = g_bny_shift[c];
    float4 r;
    r.x = fmaf(v.x, sc, sf);
    r.y = fmaf(v.y, sc, sf);
    r.z = fmaf(v.z, sc, sf);
    r.w = fmaf(v.w, sc, sf);
    reinterpret_cast<float4*>(out)[i] = r;
}

// ---------------- launch ----------------
extern "C" void kernel_launch(void* const* d_in, const int* in_sizes, int n_in,
                              void* d_out, int out_size)
{
    const float* x      = (const float*)d_in[0];
    const float* conv_w = (const float*)d_in[1];
    const float* conv_b = (const float*)d_in[2];
    const float* raw_g  = (const float*)d_in[3];
    const float* raw_b  = (const float*)d_in[4];
    const float* sp_W   = (const float*)d_in[5];
    const float* sp_b   = (const float*)d_in[6];
    const float* tp_W   = (const float*)d_in[7];
    const float* tp_b   = (const float*)d_in[8];
    const float* ps_w   = (const float*)d_in[9];
    const float* ps_b   = (const float*)d_in[10];
    const float* ps_g   = (const float*)d_in[11];
    const float* ps_bt  = (const float*)d_in[12];
    const float* fu_w   = (const float*)d_in[13];
    const float* fu_b   = (const float*)d_in[14];
    const float* fu_g   = (const float*)d_in[15];
    const float* fu_bt  = (const float*)d_in[16];
    const int*   nbr    = (const int*)d_in[17];
    float* out          = (float*)d_out;

    cudaFuncSetAttribute(k_sig, cudaFuncAttributeMaxDynamicSharedMemorySize, SIG_WORDS * 4);
    cudaFuncSetAttribute(k_fu,  cudaFuncAttributeMaxDynamicSharedMemorySize, FU_WORDS * 4);

    k_fold1 <<<1, 256>>>(sp_W, sp_b, tp_W, tp_b, ps_w, ps_b);
    k_conv  <<<dim3(JJ, BB), 256>>>(x, conv_w, conv_b);
    k_nop   <<<1, 32>>>();
    k_sig   <<<BB * JJ, 512, SIG_WORDS * 4>>>(x, nbr);
    k_reduce<<<128, 256>>>(0);
    k_fold2 <<<1, 256>>>(raw_g, raw_b, ps_g, ps_bt, fu_w, fu_b);
    k_fu    <<<BB * JJ, 512, FU_WORDS * 4>>>(x, conv_w, conv_b);
    k_reduce<<<64, 256>>>(128);
    k_bny   <<<1, 64>>>(fu_g, fu_bt);
    k_apply <<<(BB * CO * ROW) / 1024, 256>>>(out);
}